// round 1
// baseline (speedup 1.0000x reference)
#include <cuda_runtime.h>
#include <math.h>
#include <stdint.h>

#define CTX      1024
#define BROWS    16          // BS * C_IN
#define TOTAL_S  320         // NF + NC
#define NF       256
#define D_MODEL  256
#define NHEADS   16
#define DK       16
#define DFF      1024
#define NLAYERS  4
#define TGT      96
#define SEQ      (BROWS * TOTAL_S)   // 5120
#define ATTN_SCALE 0.25f             // DK^-0.5
#define LN_EPS   1e-5f

// ---------------- scratch (device globals: no allocs allowed) ----------------
__device__ float g_u[SEQ * D_MODEL];
__device__ float g_q[SEQ * D_MODEL];
__device__ float g_k[SEQ * D_MODEL];
__device__ float g_v[SEQ * D_MODEL];
__device__ float g_o[SEQ * D_MODEL];
__device__ float g_tmp[SEQ * D_MODEL];
__device__ float g_h1[SEQ * DFF];
__device__ float g_scores[BROWS * NHEADS * TOTAL_S * TOTAL_S];  // 104.9 MB
__device__ float g_mean[BROWS];
__device__ float g_std[BROWS];
__device__ float g_part[D_MODEL * BROWS * TGT];

// ---------------- RevIN stats: mean/std per (bs,c) row over CTX --------------
__global__ __launch_bounds__(256) void stats_kernel(const float* __restrict__ z) {
    int r = blockIdx.x;           // 0..15
    int tid = threadIdx.x;
    float s = 0.f, s2 = 0.f;
    for (int i = tid; i < CTX; i += 256) {
        float v = z[r * CTX + i];
        s += v; s2 += v * v;
    }
    __shared__ float rs[256], rq[256];
    rs[tid] = s; rq[tid] = s2;
    __syncthreads();
    for (int o = 128; o; o >>= 1) {
        if (tid < o) { rs[tid] += rs[tid + o]; rq[tid] += rq[tid + o]; }
        __syncthreads();
    }
    if (tid == 0) {
        float m = rs[0] / CTX;
        float var = rq[0] / CTX - m * m;
        g_mean[r] = m;
        g_std[r]  = sqrtf(var + LN_EPS);
    }
}

// ---------------- patch embed + positional add -------------------------------
__global__ __launch_bounds__(256) void embed_kernel(
    const float* __restrict__ z,
    const float* __restrict__ revin_w, const float* __restrict__ revin_b,
    const float* __restrict__ Wf, const float* __restrict__ bf,
    const float* __restrict__ Wc, const float* __restrict__ bcoarse,
    const float* __restrict__ Wpos)
{
    int bch = blockIdx.y;     // 0..15
    int s   = blockIdx.x;     // 0..319
    int d   = threadIdx.x;    // 0..255
    int c   = bch & 7;

    __shared__ float patch[32];
    int plen, stride, p;
    const float* W; const float* bias;
    if (s < NF) { plen = 8;  stride = 4;  p = s;      W = Wf; bias = bf; }
    else        { plen = 32; stride = 16; p = s - NF; W = Wc; bias = bcoarse; }

    if (d < plen) {
        int t = p * stride + d;
        if (t > CTX - 1) t = CTX - 1;   // ReplicationPad1d((0, stride))
        float zv = z[bch * CTX + t];
        patch[d] = (zv - g_mean[bch]) / g_std[bch] * revin_w[c] + revin_b[c];
    }
    __syncthreads();

    float acc = bias[d] + Wpos[s * D_MODEL + d];
    for (int i = 0; i < plen; i++) acc += patch[i] * W[i * D_MODEL + d];
    g_u[(bch * TOTAL_S + s) * D_MODEL + d] = acc;
}

// ---------------- generic tiled fp32 GEMM: C = A@B + bias, opt GELU ----------
// A [M,K] row-major, B [K,N] row-major, C [M,N]. M%64==0, N%64==0, K%16==0.
template<int EPI>
__global__ __launch_bounds__(256) void gemm_kernel(
    const float* __restrict__ A, const float* __restrict__ B,
    const float* __restrict__ bias, float* __restrict__ C,
    int M, int N, int K)
{
    __shared__ float As[16][64];
    __shared__ float Bs[16][64];
    const int bm = blockIdx.y * 64;
    const int bn = blockIdx.x * 64;
    const int tid = threadIdx.x;
    const int tx = tid & 15;
    const int ty = tid >> 4;

    float acc[4][4];
#pragma unroll
    for (int i = 0; i < 4; i++)
#pragma unroll
        for (int j = 0; j < 4; j++) acc[i][j] = 0.f;

    const int la_m = tid >> 2;
    const int la_k = (tid & 3) * 4;
    const int lb_k = tid >> 4;
    const int lb_n = (tid & 15) * 4;

    for (int k0 = 0; k0 < K; k0 += 16) {
        float4 a = *(const float4*)(A + (size_t)(bm + la_m) * K + k0 + la_k);
        As[la_k + 0][la_m] = a.x;
        As[la_k + 1][la_m] = a.y;
        As[la_k + 2][la_m] = a.z;
        As[la_k + 3][la_m] = a.w;
        *(float4*)&Bs[lb_k][lb_n] =
            *(const float4*)(B + (size_t)(k0 + lb_k) * N + bn + lb_n);
        __syncthreads();
#pragma unroll
        for (int kk = 0; kk < 16; kk++) {
            float4 av = *(const float4*)&As[kk][ty * 4];
            float4 bv = *(const float4*)&Bs[kk][tx * 4];
            float ar[4] = {av.x, av.y, av.z, av.w};
            float br[4] = {bv.x, bv.y, bv.z, bv.w};
#pragma unroll
            for (int i = 0; i < 4; i++)
#pragma unroll
                for (int j = 0; j < 4; j++) acc[i][j] += ar[i] * br[j];
        }
        __syncthreads();
    }
#pragma unroll
    for (int i = 0; i < 4; i++) {
        int row = bm + ty * 4 + i;
#pragma unroll
        for (int j = 0; j < 4; j++) {
            int col = bn + tx * 4 + j;
            float val = acc[i][j] + bias[col];
            if (EPI == 1) val = 0.5f * val * (1.0f + erff(val * 0.70710678118654752f));
            C[(size_t)row * N + col] = val;
        }
    }
}

// ---------------- fused attention per (batch-head, q-tile) -------------------
// q,k,v layout [bc][s][h][dk] (= GEMM output row-major [5120][256]).
// Writes pre-softmax scores (incl. prev) to g_scores for the next layer.
__global__ __launch_bounds__(128) void attn_kernel(int use_prev)
{
    int bh = blockIdx.y;            // 0..255
    int bc = bh >> 4, h = bh & 15;
    int q0 = blockIdx.x * 32;

    __shared__ float Ks[TOTAL_S][17];
    __shared__ float Vs[TOTAL_S][17];
    int tid = threadIdx.x;
    for (int i = tid; i < TOTAL_S * DK; i += 128) {
        int s = i >> 4, d = i & 15;
        size_t gi = ((size_t)(bc * TOTAL_S + s) << 8) + (h << 4) + d;
        Ks[s][d] = g_k[gi];
        Vs[s][d] = g_v[gi];
    }
    __syncthreads();

    int warp = tid >> 5, lane = tid & 31;
    for (int it = 0; it < 8; it++) {
        int qi = q0 + warp * 8 + it;
        const float* qp = &g_q[((size_t)(bc * TOTAL_S + qi) << 8) + (h << 4)];
        float qv[DK];
#pragma unroll
        for (int d = 0; d < DK; d++) qv[d] = qp[d];

        float* srow = &g_scores[((size_t)bh * TOTAL_S + qi) * TOTAL_S];
        float sc[10];
#pragma unroll
        for (int j = 0; j < 10; j++) {
            int kk = j * 32 + lane;
            float acc = 0.f;
#pragma unroll
            for (int d = 0; d < DK; d++) acc += qv[d] * Ks[kk][d];
            acc *= ATTN_SCALE;
            if (use_prev) acc += srow[kk];
            sc[j] = acc;
            srow[kk] = acc;       // persist for next layer's residual score
        }
        // softmax over 320 (10 regs x 32 lanes)
        float m = sc[0];
#pragma unroll
        for (int j = 1; j < 10; j++) m = fmaxf(m, sc[j]);
#pragma unroll
        for (int o = 16; o; o >>= 1) m = fmaxf(m, __shfl_xor_sync(0xffffffffu, m, o));
        float sum = 0.f;
#pragma unroll
        for (int j = 0; j < 10; j++) { sc[j] = __expf(sc[j] - m); sum += sc[j]; }
#pragma unroll
        for (int o = 16; o; o >>= 1) sum += __shfl_xor_sync(0xffffffffu, sum, o);
        float inv = 1.f / sum;

        float oacc[DK];
#pragma unroll
        for (int d = 0; d < DK; d++) oacc[d] = 0.f;
#pragma unroll
        for (int j = 0; j < 10; j++) {
            int kk = j * 32 + lane;
            float w = sc[j] * inv;
#pragma unroll
            for (int d = 0; d < DK; d++) oacc[d] += w * Vs[kk][d];
        }
#pragma unroll
        for (int d = 0; d < DK; d++) {
#pragma unroll
            for (int o = 16; o; o >>= 1)
                oacc[d] += __shfl_xor_sync(0xffffffffu, oacc[d], o);
        }
        if (lane < DK)
            g_o[((size_t)(bc * TOTAL_S + qi) << 8) + (h << 4) + lane] = oacc[lane];
    }
}

// ---------------- residual add + LayerNorm (in-place on g_u) ----------------
__global__ __launch_bounds__(256) void resid_ln_kernel(
    const float* __restrict__ delta,
    const float* __restrict__ gs, const float* __restrict__ gb)
{
    int row = blockIdx.x;     // 0..5119
    int d = threadIdx.x;      // 0..255
    size_t idx = (size_t)row * D_MODEL + d;
    float t = g_u[idx] + delta[idx];

    __shared__ float red[256];
    red[d] = t;
    __syncthreads();
    for (int o = 128; o; o >>= 1) { if (d < o) red[d] += red[d + o]; __syncthreads(); }
    float m = red[0] / D_MODEL;
    __syncthreads();
    float df = t - m;
    red[d] = df * df;
    __syncthreads();
    for (int o = 128; o; o >>= 1) { if (d < o) red[d] += red[d + o]; __syncthreads(); }
    float var = red[0] / D_MODEL;
    g_u[idx] = df * rsqrtf(var + LN_EPS) * gs[d] + gb[d];
}

// ---------------- head, stage 1: per-d partial (deterministic split-K) ------
__global__ __launch_bounds__(96) void head_partial_kernel(const float* __restrict__ Wh)
{
    int d = blockIdx.x;       // 0..255
    int t = threadIdx.x;      // 0..95
    __shared__ float usm[BROWS][TOTAL_S];
    for (int i = t; i < BROWS * TOTAL_S; i += 96) {
        int bcc = i / TOTAL_S, s = i % TOTAL_S;
        usm[bcc][s] = g_u[(size_t)(bcc * TOTAL_S + s) * D_MODEL + d];
    }
    __syncthreads();
    float acc[BROWS];
#pragma unroll
    for (int b = 0; b < BROWS; b++) acc[b] = 0.f;
    for (int s = 0; s < TOTAL_S; s++) {
        float w = Wh[((size_t)d * TOTAL_S + s) * TGT + t];
#pragma unroll
        for (int b = 0; b < BROWS; b++) acc[b] += usm[b][s] * w;
    }
#pragma unroll
    for (int b = 0; b < BROWS; b++)
        g_part[((size_t)d * BROWS + b) * TGT + t] = acc[b];
}

// ---------------- head, stage 2: reduce over d + RevIN denorm ---------------
__global__ __launch_bounds__(256) void head_reduce_kernel(
    const float* __restrict__ bh,
    const float* __restrict__ revin_w, const float* __restrict__ revin_b,
    float* __restrict__ out)
{
    int idx = blockIdx.x * blockDim.x + threadIdx.x;
    if (idx >= BROWS * TGT) return;
    int bcc = idx / TGT, t = idx % TGT;
    float acc = 0.f;
    for (int d = 0; d < D_MODEL; d++)
        acc += g_part[((size_t)d * BROWS + bcc) * TGT + t];
    acc += bh[t];
    int c = bcc & 7;
    out[idx] = (acc - revin_b[c]) / (revin_w[c] + 1e-10f) * g_std[bcc] + g_mean[bcc];
}

// ---------------- launch ------------------------------------------------------
extern "C" void kernel_launch(void* const* d_in, const int* in_sizes, int n_in,
                              void* d_out, int out_size)
{
    const float* z       = (const float*)d_in[0];
    const float* revin_w = (const float*)d_in[1];
    const float* revin_b = (const float*)d_in[2];
    const float* Wf      = (const float*)d_in[3];
    const float* bf      = (const float*)d_in[4];
    const float* Wc      = (const float*)d_in[5];
    const float* bcoarse = (const float*)d_in[6];
    const float* Wpos    = (const float*)d_in[7];
    const float* WQ      = (const float*)d_in[8];
    const float* bQ      = (const float*)d_in[9];
    const float* WK      = (const float*)d_in[10];
    const float* bK      = (const float*)d_in[11];
    const float* WV      = (const float*)d_in[12];
    const float* bV      = (const float*)d_in[13];
    const float* WO      = (const float*)d_in[14];
    const float* bO      = (const float*)d_in[15];
    const float* ln1_s   = (const float*)d_in[16];
    const float* ln1_b   = (const float*)d_in[17];
    const float* ln2_s   = (const float*)d_in[18];
    const float* ln2_b   = (const float*)d_in[19];
    const float* F1      = (const float*)d_in[20];
    const float* c1      = (const float*)d_in[21];
    const float* F2      = (const float*)d_in[22];
    const float* c2      = (const float*)d_in[23];
    const float* Wh      = (const float*)d_in[24];
    const float* bh      = (const float*)d_in[25];
    float* out = (float*)d_out;

    float *u, *q, *k, *v, *o, *tmp, *h1;
    cudaGetSymbolAddress((void**)&u,  g_u);
    cudaGetSymbolAddress((void**)&q,  g_q);
    cudaGetSymbolAddress((void**)&k,  g_k);
    cudaGetSymbolAddress((void**)&v,  g_v);
    cudaGetSymbolAddress((void**)&o,  g_o);
    cudaGetSymbolAddress((void**)&tmp, g_tmp);
    cudaGetSymbolAddress((void**)&h1, g_h1);

    stats_kernel<<<BROWS, 256>>>(z);
    embed_kernel<<<dim3(TOTAL_S, BROWS), 256>>>(z, revin_w, revin_b,
                                                Wf, bf, Wc, bcoarse, Wpos);

    for (int l = 0; l < NLAYERS; l++) {
        const float* WQl = WQ + (size_t)l * D_MODEL * D_MODEL;
        const float* WKl = WK + (size_t)l * D_MODEL * D_MODEL;
        const float* WVl = WV + (size_t)l * D_MODEL * D_MODEL;
        const float* WOl = WO + (size_t)l * D_MODEL * D_MODEL;
        const float* F1l = F1 + (size_t)l * D_MODEL * DFF;
        const float* F2l = F2 + (size_t)l * DFF * D_MODEL;

        gemm_kernel<0><<<dim3(4, 80), 256>>>(u, WQl, bQ + l * D_MODEL, q,
                                             SEQ, D_MODEL, D_MODEL);
        gemm_kernel<0><<<dim3(4, 80), 256>>>(u, WKl, bK + l * D_MODEL, k,
                                             SEQ, D_MODEL, D_MODEL);
        gemm_kernel<0><<<dim3(4, 80), 256>>>(u, WVl, bV + l * D_MODEL, v,
                                             SEQ, D_MODEL, D_MODEL);
        attn_kernel<<<dim3(10, BROWS * NHEADS), 128>>>(l > 0 ? 1 : 0);
        gemm_kernel<0><<<dim3(4, 80), 256>>>(o, WOl, bO + l * D_MODEL, tmp,
                                             SEQ, D_MODEL, D_MODEL);
        resid_ln_kernel<<<SEQ, 256>>>(tmp, ln1_s + l * D_MODEL, ln1_b + l * D_MODEL);
        gemm_kernel<1><<<dim3(16, 80), 256>>>(u, F1l, c1 + l * DFF, h1,
                                              SEQ, DFF, D_MODEL);
        gemm_kernel<0><<<dim3(4, 80), 256>>>(h1, F2l, c2 + l * D_MODEL, tmp,
                                             SEQ, D_MODEL, DFF);
        resid_ln_kernel<<<SEQ, 256>>>(tmp, ln2_s + l * D_MODEL, ln2_b + l * D_MODEL);
    }

    head_partial_kernel<<<D_MODEL, 96>>>(Wh);
    head_reduce_kernel<<<6, 256>>>(bh, revin_w, revin_b, out);
}

// round 3
// speedup vs baseline: 1.3949x; 1.3949x over previous
#include <cuda_runtime.h>
#include <cuda_bf16.h>
#include <math.h>
#include <stdint.h>

#define CTX      1024
#define BROWS    16          // BS * C_IN
#define TOTAL_S  320         // NF + NC
#define NF       256
#define D_MODEL  256
#define NHEADS   16
#define DK       16
#define DFF      1024
#define NLAYERS  4
#define TGT      96
#define SEQ      (BROWS * TOTAL_S)   // 5120
#define ATTN_SCALE 0.25f             // DK^-0.5
#define LN_EPS   1e-5f

// ---------------------------------------------------------------------------
// warp MMA helpers (sm_80+; no tcgen05 — ptxas targets sm_103 without 'a')
// ---------------------------------------------------------------------------
__device__ __forceinline__ uint32_t smem_u32(const void* p) {
    uint32_t a;
    asm("{ .reg .u64 t; cvta.to.shared.u64 t, %1; cvt.u32.u64 %0, t; }"
        : "=r"(a) : "l"(p));
    return a;
}
__device__ __forceinline__ void ldsm_x4(uint32_t& r0, uint32_t& r1,
                                        uint32_t& r2, uint32_t& r3, uint32_t addr) {
    asm volatile("ldmatrix.sync.aligned.m8n8.x4.shared.b16 {%0,%1,%2,%3}, [%4];"
                 : "=r"(r0), "=r"(r1), "=r"(r2), "=r"(r3) : "r"(addr));
}
__device__ __forceinline__ void mma_bf16(float* c, const uint32_t* a, const uint32_t* b) {
    asm volatile(
        "mma.sync.aligned.m16n8k16.row.col.f32.bf16.bf16.f32 "
        "{%0,%1,%2,%3}, {%4,%5,%6,%7}, {%8,%9}, {%0,%1,%2,%3};"
        : "+f"(c[0]), "+f"(c[1]), "+f"(c[2]), "+f"(c[3])
        : "r"(a[0]), "r"(a[1]), "r"(a[2]), "r"(a[3]), "r"(b[0]), "r"(b[1]));
}

// ---------------------------------------------------------------------------
// scratch (device globals: no allocs allowed)
// ---------------------------------------------------------------------------
__device__ __align__(256) float g_u[SEQ * D_MODEL];
__device__ __align__(256) float g_q[SEQ * D_MODEL];
__device__ __align__(256) float g_k[SEQ * D_MODEL];
__device__ __align__(256) float g_v[SEQ * D_MODEL];
__device__ __align__(256) float g_o[SEQ * D_MODEL];
__device__ __align__(256) float g_tmp[SEQ * D_MODEL];
__device__ __align__(256) float g_scores[BROWS * NHEADS * TOTAL_S * TOTAL_S];
__device__ float g_mean[BROWS];
__device__ float g_std[BROWS];
__device__ __align__(256) float g_part[D_MODEL * BROWS * TGT];

__device__ __align__(256) __nv_bfloat16 g_u_hi[SEQ * D_MODEL];
__device__ __align__(256) __nv_bfloat16 g_u_lo[SEQ * D_MODEL];
__device__ __align__(256) __nv_bfloat16 g_o_hi[SEQ * D_MODEL];
__device__ __align__(256) __nv_bfloat16 g_o_lo[SEQ * D_MODEL];
__device__ __align__(256) __nv_bfloat16 g_h1_hi[SEQ * DFF];
__device__ __align__(256) __nv_bfloat16 g_h1_lo[SEQ * DFF];
#define WOFF_Q   0
#define WOFF_K   65536
#define WOFF_V   131072
#define WOFF_O   196608
#define WOFF_F1  262144
#define WOFF_F2  524288
#define WSTRIDE  786432
__device__ __align__(256) __nv_bfloat16 g_wt_hi[NLAYERS * WSTRIDE];
__device__ __align__(256) __nv_bfloat16 g_wt_lo[NLAYERS * WSTRIDE];

// ---------------------------------------------------------------------------
// RevIN stats
// ---------------------------------------------------------------------------
__global__ __launch_bounds__(256) void stats_kernel(const float* __restrict__ z) {
    int r = blockIdx.x;
    int tid = threadIdx.x;
    float s = 0.f, s2 = 0.f;
    for (int i = tid; i < CTX; i += 256) {
        float v = z[r * CTX + i];
        s += v; s2 += v * v;
    }
    __shared__ float rs[256], rq[256];
    rs[tid] = s; rq[tid] = s2;
    __syncthreads();
    for (int o = 128; o; o >>= 1) {
        if (tid < o) { rs[tid] += rs[tid + o]; rq[tid] += rq[tid + o]; }
        __syncthreads();
    }
    if (tid == 0) {
        float m = rs[0] / CTX;
        float var = rq[0] / CTX - m * m;
        g_mean[r] = m;
        g_std[r]  = sqrtf(var + LN_EPS);
    }
}

// ---------------------------------------------------------------------------
// patch embed + positional add (+ emit bf16 split of u)
// ---------------------------------------------------------------------------
__global__ __launch_bounds__(256) void embed_kernel(
    const float* __restrict__ z,
    const float* __restrict__ revin_w, const float* __restrict__ revin_b,
    const float* __restrict__ Wf, const float* __restrict__ bf,
    const float* __restrict__ Wc, const float* __restrict__ bcoarse,
    const float* __restrict__ Wpos)
{
    int bch = blockIdx.y;
    int s   = blockIdx.x;
    int d   = threadIdx.x;
    int c   = bch & 7;

    __shared__ float patch[32];
    int plen, stride, p;
    const float* W; const float* bias;
    if (s < NF) { plen = 8;  stride = 4;  p = s;      W = Wf; bias = bf; }
    else        { plen = 32; stride = 16; p = s - NF; W = Wc; bias = bcoarse; }

    if (d < plen) {
        int t = p * stride + d;
        if (t > CTX - 1) t = CTX - 1;
        float zv = z[bch * CTX + t];
        patch[d] = (zv - g_mean[bch]) / g_std[bch] * revin_w[c] + revin_b[c];
    }
    __syncthreads();

    float acc = bias[d] + Wpos[s * D_MODEL + d];
    for (int i = 0; i < plen; i++) acc += patch[i] * W[i * D_MODEL + d];
    size_t idx = (size_t)(bch * TOTAL_S + s) * D_MODEL + d;
    g_u[idx] = acc;
    __nv_bfloat16 h = __float2bfloat16(acc);
    g_u_hi[idx] = h;
    g_u_lo[idx] = __float2bfloat16(acc - __bfloat162float(h));
}

// ---------------------------------------------------------------------------
// weight transpose + split: W [R,C] fp32 -> out [C,R] bf16 hi/lo, layered
// ---------------------------------------------------------------------------
__global__ __launch_bounds__(256) void wsplitT_kernel(
    const float* __restrict__ W, __nv_bfloat16* __restrict__ hi,
    __nv_bfloat16* __restrict__ lo, int R, int C,
    size_t lstride_in, size_t lstride_out)
{
    int l = blockIdx.z;
    const float* Wl = W + (size_t)l * lstride_in;
    __shared__ float t[32][33];
    int c0 = blockIdx.x * 32, r0 = blockIdx.y * 32;
    int tx = threadIdx.x & 31, ty = threadIdx.x >> 5;
#pragma unroll
    for (int i = 0; i < 32; i += 8)
        t[ty + i][tx] = Wl[(size_t)(r0 + ty + i) * C + c0 + tx];
    __syncthreads();
#pragma unroll
    for (int i = 0; i < 32; i += 8) {
        float x = t[tx][ty + i];
        size_t oi = (size_t)l * lstride_out + (size_t)(c0 + ty + i) * R + (r0 + tx);
        __nv_bfloat16 h = __float2bfloat16(x);
        hi[oi] = h;
        lo[oi] = __float2bfloat16(x - __bfloat162float(h));
    }
}

// ---------------------------------------------------------------------------
// elementwise split
// ---------------------------------------------------------------------------
__global__ __launch_bounds__(256) void asplit_kernel(
    const float* __restrict__ x, __nv_bfloat16* __restrict__ hi,
    __nv_bfloat16* __restrict__ lo, int n)
{
    int i = blockIdx.x * 256 + threadIdx.x;
    if (i >= n) return;
    float v = x[i];
    __nv_bfloat16 h = __float2bfloat16(v);
    hi[i] = h;
    lo[i] = __float2bfloat16(v - __bfloat162float(h));
}

// ---------------------------------------------------------------------------
// HMMA bf16x3 GEMM: C[M,N] = A[M,K] @ B^T  (B stored [N,K] K-major)
// CTA tile 128x128, K-chunk 64, 8 warps each 32x64.
// EPI=0: Cf = val + bias.  EPI=1: GELU(val+bias) -> bf16 hi/lo split.
// ---------------------------------------------------------------------------
#define ASTRIDE 72                       // bf16 elems per smem row (pad 64->72)
#define GEMM_SMEM (4 * 128 * ASTRIDE * 2)  // 73728 B

template<int EPI>
__global__ __launch_bounds__(256) void gemm_tc(
    const __nv_bfloat16* __restrict__ Ah, const __nv_bfloat16* __restrict__ Al,
    const __nv_bfloat16* __restrict__ Bh, const __nv_bfloat16* __restrict__ Bl,
    const float* __restrict__ bias,
    float* __restrict__ Cf,
    __nv_bfloat16* __restrict__ Chi, __nv_bfloat16* __restrict__ Clo,
    int N, int K)
{
    extern __shared__ __nv_bfloat16 sm[];
    __nv_bfloat16* sAh = sm;
    __nv_bfloat16* sAl = sAh + 128 * ASTRIDE;
    __nv_bfloat16* sBh = sAl + 128 * ASTRIDE;
    __nv_bfloat16* sBl = sBh + 128 * ASTRIDE;
    const uint32_t uAh = smem_u32(sAh), uAl = smem_u32(sAl);
    const uint32_t uBh = smem_u32(sBh), uBl = smem_u32(sBl);

    const int tid = threadIdx.x;
    const int bm = blockIdx.y * 128, bn = blockIdx.x * 128;
    const int warp = tid >> 5, lane = tid & 31;
    const int wm = warp >> 1, wn = warp & 1;

    float acc[2][8][4];
#pragma unroll
    for (int mt = 0; mt < 2; mt++)
#pragma unroll
        for (int nt = 0; nt < 8; nt++)
#pragma unroll
            for (int i = 0; i < 4; i++) acc[mt][nt][i] = 0.f;

    // ldmatrix per-lane source mapping
    const int gg = lane >> 3, l7 = lane & 7;
    const int a_row = (gg & 1) * 8 + l7;
    const int a_kb  = (gg >> 1) * 16;        // bytes
    const int b_row = (gg >> 1) * 8 + l7;
    const int b_kb  = (gg & 1) * 16;

    const int sr = tid >> 3, sc = (tid & 7) * 8;   // staging: row, col(elems)

    for (int k0 = 0; k0 < K; k0 += 64) {
#pragma unroll
        for (int i = 0; i < 4; i++) {
            int r = sr + i * 32;
            size_t gA = ((size_t)(bm + r) * K + k0 + sc) >> 3;
            size_t gB = ((size_t)(bn + r) * K + k0 + sc) >> 3;
            int so = r * ASTRIDE + sc;
            *(uint4*)&sAh[so] = ((const uint4*)Ah)[gA];
            *(uint4*)&sAl[so] = ((const uint4*)Al)[gA];
            *(uint4*)&sBh[so] = ((const uint4*)Bh)[gB];
            *(uint4*)&sBl[so] = ((const uint4*)Bl)[gB];
        }
        __syncthreads();

#pragma unroll
        for (int ks = 0; ks < 4; ks++) {
            uint32_t ah[2][4], al[2][4], bh[8][2], bl[8][2];
#pragma unroll
            for (int mt = 0; mt < 2; mt++) {
                int row = wm * 32 + mt * 16 + a_row;
                uint32_t off = (uint32_t)(row * ASTRIDE * 2 + ks * 32 + a_kb);
                ldsm_x4(ah[mt][0], ah[mt][1], ah[mt][2], ah[mt][3], uAh + off);
                ldsm_x4(al[mt][0], al[mt][1], al[mt][2], al[mt][3], uAl + off);
            }
#pragma unroll
            for (int j = 0; j < 4; j++) {
                int row = wn * 64 + j * 16 + b_row;
                uint32_t off = (uint32_t)(row * ASTRIDE * 2 + ks * 32 + b_kb);
                uint32_t r0, r1, r2, r3;
                ldsm_x4(r0, r1, r2, r3, uBh + off);
                bh[2 * j][0] = r0; bh[2 * j][1] = r1;
                bh[2 * j + 1][0] = r2; bh[2 * j + 1][1] = r3;
                ldsm_x4(r0, r1, r2, r3, uBl + off);
                bl[2 * j][0] = r0; bl[2 * j][1] = r1;
                bl[2 * j + 1][0] = r2; bl[2 * j + 1][1] = r3;
            }
#pragma unroll
            for (int mt = 0; mt < 2; mt++)
#pragma unroll
                for (int nt = 0; nt < 8; nt++) {
                    mma_bf16(acc[mt][nt], ah[mt], bh[nt]);
                    mma_bf16(acc[mt][nt], ah[mt], bl[nt]);
                    mma_bf16(acc[mt][nt], al[mt], bh[nt]);
                }
        }
        __syncthreads();
    }

    // epilogue: thread (lane>>2) rows, (lane&3)*2 cols within each m16n8
#pragma unroll
    for (int mt = 0; mt < 2; mt++) {
        int row0 = bm + wm * 32 + mt * 16 + (lane >> 2);
#pragma unroll
        for (int nt = 0; nt < 8; nt++) {
            int col = bn + wn * 64 + nt * 8 + (lane & 3) * 2;
            float b0 = bias[col], b1 = bias[col + 1];
            float v0 = acc[mt][nt][0] + b0, v1 = acc[mt][nt][1] + b1;
            float v2 = acc[mt][nt][2] + b0, v3 = acc[mt][nt][3] + b1;
            if (EPI == 0) {
                float2 p0 = {v0, v1}, p1 = {v2, v3};
                *(float2*)&Cf[(size_t)row0 * N + col] = p0;
                *(float2*)&Cf[(size_t)(row0 + 8) * N + col] = p1;
            } else {
                v0 = 0.5f * v0 * (1.0f + erff(v0 * 0.7071067811865475f));
                v1 = 0.5f * v1 * (1.0f + erff(v1 * 0.7071067811865475f));
                v2 = 0.5f * v2 * (1.0f + erff(v2 * 0.7071067811865475f));
                v3 = 0.5f * v3 * (1.0f + erff(v3 * 0.7071067811865475f));
                __nv_bfloat162 hh, ll;
                hh.x = __float2bfloat16(v0); hh.y = __float2bfloat16(v1);
                ll.x = __float2bfloat16(v0 - __bfloat162float(hh.x));
                ll.y = __float2bfloat16(v1 - __bfloat162float(hh.y));
                *(__nv_bfloat162*)&Chi[(size_t)row0 * N + col] = hh;
                *(__nv_bfloat162*)&Clo[(size_t)row0 * N + col] = ll;
                hh.x = __float2bfloat16(v2); hh.y = __float2bfloat16(v3);
                ll.x = __float2bfloat16(v2 - __bfloat162float(hh.x));
                ll.y = __float2bfloat16(v3 - __bfloat162float(hh.y));
                *(__nv_bfloat162*)&Chi[(size_t)(row0 + 8) * N + col] = hh;
                *(__nv_bfloat162*)&Clo[(size_t)(row0 + 8) * N + col] = ll;
            }
        }
    }
}

// ---------------------------------------------------------------------------
// fused attention
// ---------------------------------------------------------------------------
__global__ __launch_bounds__(128) void attn_kernel(int use_prev)
{
    int bh = blockIdx.y;
    int bc = bh >> 4, h = bh & 15;
    int q0 = blockIdx.x * 32;

    __shared__ float Ks[TOTAL_S][17];
    __shared__ float Vs[TOTAL_S][17];
    int tid = threadIdx.x;
    for (int i = tid; i < TOTAL_S * DK; i += 128) {
        int s = i >> 4, d = i & 15;
        size_t gi = ((size_t)(bc * TOTAL_S + s) << 8) + (h << 4) + d;
        Ks[s][d] = g_k[gi];
        Vs[s][d] = g_v[gi];
    }
    __syncthreads();

    int warp = tid >> 5, lane = tid & 31;
    for (int it = 0; it < 8; it++) {
        int qi = q0 + warp * 8 + it;
        const float* qp = &g_q[((size_t)(bc * TOTAL_S + qi) << 8) + (h << 4)];
        float qv[DK];
#pragma unroll
        for (int d = 0; d < DK; d++) qv[d] = qp[d];

        float* srow = &g_scores[((size_t)bh * TOTAL_S + qi) * TOTAL_S];
        float sc[10];
#pragma unroll
        for (int j = 0; j < 10; j++) {
            int kk = j * 32 + lane;
            float acc = 0.f;
#pragma unroll
            for (int d = 0; d < DK; d++) acc += qv[d] * Ks[kk][d];
            acc *= ATTN_SCALE;
            if (use_prev) acc += srow[kk];
            sc[j] = acc;
            srow[kk] = acc;
        }
        float m = sc[0];
#pragma unroll
        for (int j = 1; j < 10; j++) m = fmaxf(m, sc[j]);
#pragma unroll
        for (int o = 16; o; o >>= 1) m = fmaxf(m, __shfl_xor_sync(0xffffffffu, m, o));
        float sum = 0.f;
#pragma unroll
        for (int j = 0; j < 10; j++) { sc[j] = __expf(sc[j] - m); sum += sc[j]; }
#pragma unroll
        for (int o = 16; o; o >>= 1) sum += __shfl_xor_sync(0xffffffffu, sum, o);
        float inv = 1.f / sum;

        float oacc[DK];
#pragma unroll
        for (int d = 0; d < DK; d++) oacc[d] = 0.f;
#pragma unroll
        for (int j = 0; j < 10; j++) {
            int kk = j * 32 + lane;
            float wgt = sc[j] * inv;
#pragma unroll
            for (int d = 0; d < DK; d++) oacc[d] += wgt * Vs[kk][d];
        }
#pragma unroll
        for (int d = 0; d < DK; d++) {
#pragma unroll
            for (int o = 16; o; o >>= 1)
                oacc[d] += __shfl_xor_sync(0xffffffffu, oacc[d], o);
        }
        if (lane < DK)
            g_o[((size_t)(bc * TOTAL_S + qi) << 8) + (h << 4) + lane] = oacc[lane];
    }
}

// ---------------------------------------------------------------------------
// residual add + LayerNorm (+ emit bf16 split of new u)
// ---------------------------------------------------------------------------
__global__ __launch_bounds__(256) void resid_ln_kernel(
    const float* __restrict__ delta,
    const float* __restrict__ gs, const float* __restrict__ gb)
{
    int row = blockIdx.x;
    int d = threadIdx.x;
    size_t idx = (size_t)row * D_MODEL + d;
    float t = g_u[idx] + delta[idx];

    __shared__ float red[256];
    red[d] = t;
    __syncthreads();
    for (int o = 128; o; o >>= 1) { if (d < o) red[d] += red[d + o]; __syncthreads(); }
    float m = red[0] / D_MODEL;
    __syncthreads();
    float df = t - m;
    red[d] = df * df;
    __syncthreads();
    for (int o = 128; o; o >>= 1) { if (d < o) red[d] += red[d + o]; __syncthreads(); }
    float var = red[0] / D_MODEL;
    float y = df * rsqrtf(var + LN_EPS) * gs[d] + gb[d];
    g_u[idx] = y;
    __nv_bfloat16 h = __float2bfloat16(y);
    g_u_hi[idx] = h;
    g_u_lo[idx] = __float2bfloat16(y - __bfloat162float(h));
}

// ---------------------------------------------------------------------------
// head
// ---------------------------------------------------------------------------
__global__ __launch_bounds__(96) void head_partial_kernel(const float* __restrict__ Wh)
{
    int d = blockIdx.x;
    int t = threadIdx.x;
    __shared__ float usm[BROWS][TOTAL_S];
    for (int i = t; i < BROWS * TOTAL_S; i += 96) {
        int bcc = i / TOTAL_S, s = i % TOTAL_S;
        usm[bcc][s] = g_u[(size_t)(bcc * TOTAL_S + s) * D_MODEL + d];
    }
    __syncthreads();
    float acc[BROWS];
#pragma unroll
    for (int b = 0; b < BROWS; b++) acc[b] = 0.f;
    for (int s = 0; s < TOTAL_S; s++) {
        float w = Wh[((size_t)d * TOTAL_S + s) * TGT + t];
#pragma unroll
        for (int b = 0; b < BROWS; b++) acc[b] += usm[b][s] * w;
    }
#pragma unroll
    for (int b = 0; b < BROWS; b++)
        g_part[((size_t)d * BROWS + b) * TGT + t] = acc[b];
}

__global__ __launch_bounds__(256) void head_reduce_kernel(
    const float* __restrict__ bh,
    const float* __restrict__ revin_w, const float* __restrict__ revin_b,
    float* __restrict__ out)
{
    int idx = blockIdx.x * blockDim.x + threadIdx.x;
    if (idx >= BROWS * TGT) return;
    int bcc = idx / TGT, t = idx % TGT;
    float acc = 0.f;
    for (int d = 0; d < D_MODEL; d++)
        acc += g_part[((size_t)d * BROWS + bcc) * TGT + t];
    acc += bh[t];
    int c = bcc & 7;
    out[idx] = (acc - revin_b[c]) / (revin_w[c] + 1e-10f) * g_std[bcc] + g_mean[bcc];
}

// ---------------------------------------------------------------------------
// launch
// ---------------------------------------------------------------------------
extern "C" void kernel_launch(void* const* d_in, const int* in_sizes, int n_in,
                              void* d_out, int out_size)
{
    const float* z       = (const float*)d_in[0];
    const float* revin_w = (const float*)d_in[1];
    const float* revin_b = (const float*)d_in[2];
    const float* Wf      = (const float*)d_in[3];
    const float* bf      = (const float*)d_in[4];
    const float* Wc      = (const float*)d_in[5];
    const float* bcoarse = (const float*)d_in[6];
    const float* Wpos    = (const float*)d_in[7];
    const float* WQ      = (const float*)d_in[8];
    const float* bQ      = (const float*)d_in[9];
    const float* WK      = (const float*)d_in[10];
    const float* bK      = (const float*)d_in[11];
    const float* WV      = (const float*)d_in[12];
    const float* bV      = (const float*)d_in[13];
    const float* WO      = (const float*)d_in[14];
    const float* bO      = (const float*)d_in[15];
    const float* ln1_s   = (const float*)d_in[16];
    const float* ln1_b   = (const float*)d_in[17];
    const float* ln2_s   = (const float*)d_in[18];
    const float* ln2_b   = (const float*)d_in[19];
    const float* F1      = (const float*)d_in[20];
    const float* c1      = (const float*)d_in[21];
    const float* F2      = (const float*)d_in[22];
    const float* c2      = (const float*)d_in[23];
    const float* Wh      = (const float*)d_in[24];
    const float* bh      = (const float*)d_in[25];
    float* out = (float*)d_out;

    float *u, *q, *k, *v, *o, *tmp;
    __nv_bfloat16 *uh, *ul, *oh, *ol, *h1h, *h1l, *wth, *wtl;
    cudaGetSymbolAddress((void**)&u,   g_u);
    cudaGetSymbolAddress((void**)&q,   g_q);
    cudaGetSymbolAddress((void**)&k,   g_k);
    cudaGetSymbolAddress((void**)&v,   g_v);
    cudaGetSymbolAddress((void**)&o,   g_o);
    cudaGetSymbolAddress((void**)&tmp, g_tmp);
    cudaGetSymbolAddress((void**)&uh,  g_u_hi);
    cudaGetSymbolAddress((void**)&ul,  g_u_lo);
    cudaGetSymbolAddress((void**)&oh,  g_o_hi);
    cudaGetSymbolAddress((void**)&ol,  g_o_lo);
    cudaGetSymbolAddress((void**)&h1h, g_h1_hi);
    cudaGetSymbolAddress((void**)&h1l, g_h1_lo);
    cudaGetSymbolAddress((void**)&wth, g_wt_hi);
    cudaGetSymbolAddress((void**)&wtl, g_wt_lo);

    cudaFuncSetAttribute(gemm_tc<0>, cudaFuncAttributeMaxDynamicSharedMemorySize, GEMM_SMEM);
    cudaFuncSetAttribute(gemm_tc<1>, cudaFuncAttributeMaxDynamicSharedMemorySize, GEMM_SMEM);

    wsplitT_kernel<<<dim3(8, 8, NLAYERS), 256>>>(WQ, wth + WOFF_Q,  wtl + WOFF_Q,  256, 256, 65536, WSTRIDE);
    wsplitT_kernel<<<dim3(8, 8, NLAYERS), 256>>>(WK, wth + WOFF_K,  wtl + WOFF_K,  256, 256, 65536, WSTRIDE);
    wsplitT_kernel<<<dim3(8, 8, NLAYERS), 256>>>(WV, wth + WOFF_V,  wtl + WOFF_V,  256, 256, 65536, WSTRIDE);
    wsplitT_kernel<<<dim3(8, 8, NLAYERS), 256>>>(WO, wth + WOFF_O,  wtl + WOFF_O,  256, 256, 65536, WSTRIDE);
    wsplitT_kernel<<<dim3(32, 8, NLAYERS), 256>>>(F1, wth + WOFF_F1, wtl + WOFF_F1, 256, 1024, 262144, WSTRIDE);
    wsplitT_kernel<<<dim3(8, 32, NLAYERS), 256>>>(F2, wth + WOFF_F2, wtl + WOFF_F2, 1024, 256, 262144, WSTRIDE);

    stats_kernel<<<BROWS, 256>>>(z);
    embed_kernel<<<dim3(TOTAL_S, BROWS), 256>>>(z, revin_w, revin_b,
                                                Wf, bf, Wc, bcoarse, Wpos);

    const dim3 grid256(2, 40);   // N=256
    const dim3 grid1024(8, 40);  // N=1024

    for (int l = 0; l < NLAYERS; l++) {
        const size_t L = (size_t)l * WSTRIDE;
        gemm_tc<0><<<grid256, 256, GEMM_SMEM>>>(uh, ul, wth + L + WOFF_Q, wtl + L + WOFF_Q,
                                                bQ + l * D_MODEL, q, nullptr, nullptr, D_MODEL, D_MODEL);
        gemm_tc<0><<<grid256, 256, GEMM_SMEM>>>(uh, ul, wth + L + WOFF_K, wtl + L + WOFF_K,
                                                bK + l * D_MODEL, k, nullptr, nullptr, D_MODEL, D_MODEL);
        gemm_tc<0><<<grid256, 256, GEMM_SMEM>>>(uh, ul, wth + L + WOFF_V, wtl + L + WOFF_V,
                                                bV + l * D_MODEL, v, nullptr, nullptr, D_MODEL, D_MODEL);
        attn_kernel<<<dim3(10, BROWS * NHEADS), 128>>>(l > 0 ? 1 : 0);
        asplit_kernel<<<(SEQ * D_MODEL + 255) / 256, 256>>>(o, oh, ol, SEQ * D_MODEL);
        gemm_tc<0><<<grid256, 256, GEMM_SMEM>>>(oh, ol, wth + L + WOFF_O, wtl + L + WOFF_O,
                                                bO + l * D_MODEL, tmp, nullptr, nullptr, D_MODEL, D_MODEL);
        resid_ln_kernel<<<SEQ, 256>>>(tmp, ln1_s + l * D_MODEL, ln1_b + l * D_MODEL);
        gemm_tc<1><<<grid1024, 256, GEMM_SMEM>>>(uh, ul, wth + L + WOFF_F1, wtl + L + WOFF_F1,
                                                 c1 + l * DFF, nullptr, h1h, h1l, DFF, D_MODEL);
        gemm_tc<0><<<grid256, 256, GEMM_SMEM>>>(h1h, h1l, wth + L + WOFF_F2, wtl + L + WOFF_F2,
                                                c2 + l * D_MODEL, tmp, nullptr, nullptr, D_MODEL, DFF);
        resid_ln_kernel<<<SEQ, 256>>>(tmp, ln2_s + l * D_MODEL, ln2_b + l * D_MODEL);
    }

    head_partial_kernel<<<D_MODEL, 96>>>(Wh);
    head_reduce_kernel<<<6, 256>>>(bh, revin_w, revin_b, out);
}

// round 4
// speedup vs baseline: 1.5055x; 1.0792x over previous
#include <cuda_runtime.h>
#include <cuda_bf16.h>
#include <math.h>
#include <stdint.h>

#define CTX      1024
#define BROWS    16
#define TOTAL_S  320
#define NF       256
#define D_MODEL  256
#define NHEADS   16
#define DK       16
#define DFF      1024
#define NLAYERS  4
#define TGT      96
#define SEQ      (BROWS * TOTAL_S)   // 5120
#define ATTN_SCALE 0.25f
#define LN_EPS   1e-5f

// ---------------------------------------------------------------------------
// warp MMA + cp.async helpers (sm_80+ path; tcgen05 unavailable at sm_103)
// ---------------------------------------------------------------------------
__device__ __forceinline__ uint32_t smem_u32(const void* p) {
    uint32_t a;
    asm("{ .reg .u64 t; cvta.to.shared.u64 t, %1; cvt.u32.u64 %0, t; }"
        : "=r"(a) : "l"(p));
    return a;
}
__device__ __forceinline__ void ldsm_x4(uint32_t& r0, uint32_t& r1,
                                        uint32_t& r2, uint32_t& r3, uint32_t addr) {
    asm volatile("ldmatrix.sync.aligned.m8n8.x4.shared.b16 {%0,%1,%2,%3}, [%4];"
                 : "=r"(r0), "=r"(r1), "=r"(r2), "=r"(r3) : "r"(addr));
}
__device__ __forceinline__ void mma_bf16(float* c, const uint32_t* a, const uint32_t* b) {
    asm volatile(
        "mma.sync.aligned.m16n8k16.row.col.f32.bf16.bf16.f32 "
        "{%0,%1,%2,%3}, {%4,%5,%6,%7}, {%8,%9}, {%0,%1,%2,%3};"
        : "+f"(c[0]), "+f"(c[1]), "+f"(c[2]), "+f"(c[3])
        : "r"(a[0]), "r"(a[1]), "r"(a[2]), "r"(a[3]), "r"(b[0]), "r"(b[1]));
}
#define CP_ASYNC16(dst, src) \
    asm volatile("cp.async.cg.shared.global [%0], [%1], 16;" :: "r"(dst), "l"(src))
#define CP_COMMIT() asm volatile("cp.async.commit_group;" ::: "memory")
#define CP_WAIT0()  asm volatile("cp.async.wait_group 0;" ::: "memory")

// ---------------------------------------------------------------------------
// scratch
// ---------------------------------------------------------------------------
__device__ __align__(256) float g_u[SEQ * D_MODEL];
__device__ __align__(256) float g_qkv[SEQ * 768];
__device__ __align__(256) float g_tmp[SEQ * D_MODEL];
__device__ __align__(256) float g_scores[BROWS * NHEADS * TOTAL_S * TOTAL_S];
__device__ float g_mean[BROWS];
__device__ float g_std[BROWS];
__device__ __align__(256) float g_part[D_MODEL * BROWS * TGT];
__device__ __align__(256) float g_bqkv[NLAYERS * 768];

__device__ __align__(256) __nv_bfloat16 g_u_hi[SEQ * D_MODEL];
__device__ __align__(256) __nv_bfloat16 g_u_lo[SEQ * D_MODEL];
__device__ __align__(256) __nv_bfloat16 g_o_hi[SEQ * D_MODEL];
__device__ __align__(256) __nv_bfloat16 g_o_lo[SEQ * D_MODEL];
__device__ __align__(256) __nv_bfloat16 g_h1_hi[SEQ * DFF];
__device__ __align__(256) __nv_bfloat16 g_h1_lo[SEQ * DFF];
#define WOFF_Q   0
#define WOFF_K   65536
#define WOFF_V   131072
#define WOFF_O   196608
#define WOFF_F1  262144
#define WOFF_F2  524288
#define WSTRIDE  786432
__device__ __align__(256) __nv_bfloat16 g_wt_hi[NLAYERS * WSTRIDE];
__device__ __align__(256) __nv_bfloat16 g_wt_lo[NLAYERS * WSTRIDE];

// ---------------------------------------------------------------------------
__global__ __launch_bounds__(256) void stats_kernel(const float* __restrict__ z) {
    int r = blockIdx.x;
    int tid = threadIdx.x;
    float s = 0.f, s2 = 0.f;
    for (int i = tid; i < CTX; i += 256) {
        float v = z[r * CTX + i];
        s += v; s2 += v * v;
    }
    __shared__ float rs[256], rq[256];
    rs[tid] = s; rq[tid] = s2;
    __syncthreads();
    for (int o = 128; o; o >>= 1) {
        if (tid < o) { rs[tid] += rs[tid + o]; rq[tid] += rq[tid + o]; }
        __syncthreads();
    }
    if (tid == 0) {
        float m = rs[0] / CTX;
        float var = rq[0] / CTX - m * m;
        g_mean[r] = m;
        g_std[r]  = sqrtf(var + LN_EPS);
    }
}

// ---------------------------------------------------------------------------
__global__ __launch_bounds__(256) void embed_kernel(
    const float* __restrict__ z,
    const float* __restrict__ revin_w, const float* __restrict__ revin_b,
    const float* __restrict__ Wf, const float* __restrict__ bf,
    const float* __restrict__ Wc, const float* __restrict__ bcoarse,
    const float* __restrict__ Wpos)
{
    int bch = blockIdx.y;
    int s   = blockIdx.x;
    int d   = threadIdx.x;
    int c   = bch & 7;

    __shared__ float patch[32];
    int plen, stride, p;
    const float* W; const float* bias;
    if (s < NF) { plen = 8;  stride = 4;  p = s;      W = Wf; bias = bf; }
    else        { plen = 32; stride = 16; p = s - NF; W = Wc; bias = bcoarse; }

    if (d < plen) {
        int t = p * stride + d;
        if (t > CTX - 1) t = CTX - 1;
        float zv = z[bch * CTX + t];
        patch[d] = (zv - g_mean[bch]) / g_std[bch] * revin_w[c] + revin_b[c];
    }
    __syncthreads();

    float acc = bias[d] + Wpos[s * D_MODEL + d];
    for (int i = 0; i < plen; i++) acc += patch[i] * W[i * D_MODEL + d];
    size_t idx = (size_t)(bch * TOTAL_S + s) * D_MODEL + d;
    g_u[idx] = acc;
    __nv_bfloat16 h = __float2bfloat16(acc);
    g_u_hi[idx] = h;
    g_u_lo[idx] = __float2bfloat16(acc - __bfloat162float(h));
}

// ---------------------------------------------------------------------------
__global__ __launch_bounds__(256) void wsplitT_kernel(
    const float* __restrict__ W, __nv_bfloat16* __restrict__ hi,
    __nv_bfloat16* __restrict__ lo, int R, int C,
    size_t lstride_in, size_t lstride_out)
{
    int l = blockIdx.z;
    const float* Wl = W + (size_t)l * lstride_in;
    __shared__ float t[32][33];
    int c0 = blockIdx.x * 32, r0 = blockIdx.y * 32;
    int tx = threadIdx.x & 31, ty = threadIdx.x >> 5;
#pragma unroll
    for (int i = 0; i < 32; i += 8)
        t[ty + i][tx] = Wl[(size_t)(r0 + ty + i) * C + c0 + tx];
    __syncthreads();
#pragma unroll
    for (int i = 0; i < 32; i += 8) {
        float x = t[tx][ty + i];
        size_t oi = (size_t)l * lstride_out + (size_t)(c0 + ty + i) * R + (r0 + tx);
        __nv_bfloat16 h = __float2bfloat16(x);
        hi[oi] = h;
        lo[oi] = __float2bfloat16(x - __bfloat162float(h));
    }
}

__global__ __launch_bounds__(256) void biaspack_kernel(
    const float* __restrict__ bQ, const float* __restrict__ bK,
    const float* __restrict__ bV)
{
    int i = blockIdx.x * 256 + threadIdx.x;
    if (i >= NLAYERS * 768) return;
    int l = i / 768, j = i % 768;
    float v = (j < 256) ? bQ[l * 256 + j]
            : (j < 512) ? bK[l * 256 + j - 256]
                        : bV[l * 256 + j - 512];
    g_bqkv[i] = v;
}

// ---------------------------------------------------------------------------
// HMMA bf16x3 GEMM, cp.async 2-stage pipeline. MT = CTA M-tile (64|128).
// ---------------------------------------------------------------------------
#define ASTRIDE 72

template<int EPI, int MT>
__global__ __launch_bounds__(256) void gemm_tc(
    const __nv_bfloat16* __restrict__ Ah, const __nv_bfloat16* __restrict__ Al,
    const __nv_bfloat16* __restrict__ Bh, const __nv_bfloat16* __restrict__ Bl,
    const float* __restrict__ bias,
    float* __restrict__ Cf,
    __nv_bfloat16* __restrict__ Chi, __nv_bfloat16* __restrict__ Clo,
    int N, int K)
{
    constexpr int WNs = (MT == 128) ? 2 : 4;
    constexpr int NT  = 16 / WNs;
    constexpr int BUF_A = MT * ASTRIDE * 2;
    constexpr int BUF_B = 128 * ASTRIDE * 2;
    constexpr int STAGE = 2 * BUF_A + 2 * BUF_B;

    extern __shared__ char smem[];
    const uint32_t sbase = smem_u32(smem);

    const int tid = threadIdx.x;
    const int bm = blockIdx.y * MT, bn = blockIdx.x * 128;
    const int warp = tid >> 5, lane = tid & 31;
    const int wm = warp / WNs, wn = warp % WNs;

    const int sr = tid >> 3, sc = (tid & 7) * 8;

    float acc[2][NT][4];
#pragma unroll
    for (int mt = 0; mt < 2; mt++)
#pragma unroll
        for (int nt = 0; nt < NT; nt++)
#pragma unroll
            for (int i = 0; i < 4; i++) acc[mt][nt][i] = 0.f;

    const int gg = lane >> 3, l7 = lane & 7;
    const int a_row = (gg & 1) * 8 + l7;
    const int a_kb  = (gg >> 1) * 16;
    const int b_row = (gg >> 1) * 8 + l7;
    const int b_kb  = (gg & 1) * 16;

    const int nchunk = K >> 6;

#define STAGE_LOAD(kc, s) do { \
        const int _k0 = (kc) << 6; \
        uint32_t _base = sbase + (s) * STAGE; \
        _Pragma("unroll") \
        for (int i = 0; i < MT / 32; i++) { \
            int r = sr + i * 32; \
            uint32_t so = _base + r * 144 + sc * 2; \
            CP_ASYNC16(so, Ah + (size_t)(bm + r) * K + _k0 + sc); \
            CP_ASYNC16(so + BUF_A, Al + (size_t)(bm + r) * K + _k0 + sc); \
        } \
        _Pragma("unroll") \
        for (int i = 0; i < 4; i++) { \
            int r = sr + i * 32; \
            uint32_t so = _base + 2 * BUF_A + r * 144 + sc * 2; \
            CP_ASYNC16(so, Bh + (size_t)(bn + r) * K + _k0 + sc); \
            CP_ASYNC16(so + BUF_B, Bl + (size_t)(bn + r) * K + _k0 + sc); \
        } \
        CP_COMMIT(); \
    } while (0)

    STAGE_LOAD(0, 0);

    for (int kc = 0; kc < nchunk; kc++) {
        CP_WAIT0();
        __syncthreads();
        if (kc + 1 < nchunk) STAGE_LOAD(kc + 1, (kc + 1) & 1);

        const uint32_t base = sbase + (kc & 1) * STAGE;
        const uint32_t uAh = base, uAl = base + BUF_A;
        const uint32_t uBh = base + 2 * BUF_A, uBl = uBh + BUF_B;

#pragma unroll
        for (int ks = 0; ks < 4; ks++) {
            uint32_t ah[2][4], al[2][4], bh[NT][2], bl[NT][2];
#pragma unroll
            for (int mt = 0; mt < 2; mt++) {
                int row = wm * 32 + mt * 16 + a_row;
                uint32_t off = (uint32_t)(row * 144 + ks * 32 + a_kb);
                ldsm_x4(ah[mt][0], ah[mt][1], ah[mt][2], ah[mt][3], uAh + off);
                ldsm_x4(al[mt][0], al[mt][1], al[mt][2], al[mt][3], uAl + off);
            }
#pragma unroll
            for (int j = 0; j < NT / 2; j++) {
                int row = wn * (128 / WNs) + j * 16 + b_row;
                uint32_t off = (uint32_t)(row * 144 + ks * 32 + b_kb);
                uint32_t r0, r1, r2, r3;
                ldsm_x4(r0, r1, r2, r3, uBh + off);
                bh[2 * j][0] = r0; bh[2 * j][1] = r1;
                bh[2 * j + 1][0] = r2; bh[2 * j + 1][1] = r3;
                ldsm_x4(r0, r1, r2, r3, uBl + off);
                bl[2 * j][0] = r0; bl[2 * j][1] = r1;
                bl[2 * j + 1][0] = r2; bl[2 * j + 1][1] = r3;
            }
#pragma unroll
            for (int mt = 0; mt < 2; mt++)
#pragma unroll
                for (int nt = 0; nt < NT; nt++) {
                    mma_bf16(acc[mt][nt], ah[mt], bh[nt]);
                    mma_bf16(acc[mt][nt], ah[mt], bl[nt]);
                    mma_bf16(acc[mt][nt], al[mt], bh[nt]);
                }
        }
        __syncthreads();
    }
#undef STAGE_LOAD

#pragma unroll
    for (int mt = 0; mt < 2; mt++) {
        int row0 = bm + wm * 32 + mt * 16 + (lane >> 2);
#pragma unroll
        for (int nt = 0; nt < NT; nt++) {
            int col = bn + wn * (128 / WNs) + nt * 8 + (lane & 3) * 2;
            float b0 = bias[col], b1 = bias[col + 1];
            float v0 = acc[mt][nt][0] + b0, v1 = acc[mt][nt][1] + b1;
            float v2 = acc[mt][nt][2] + b0, v3 = acc[mt][nt][3] + b1;
            if (EPI == 0) {
                float2 p0 = {v0, v1}, p1 = {v2, v3};
                *(float2*)&Cf[(size_t)row0 * N + col] = p0;
                *(float2*)&Cf[(size_t)(row0 + 8) * N + col] = p1;
            } else {
                v0 = 0.5f * v0 * (1.0f + erff(v0 * 0.7071067811865475f));
                v1 = 0.5f * v1 * (1.0f + erff(v1 * 0.7071067811865475f));
                v2 = 0.5f * v2 * (1.0f + erff(v2 * 0.7071067811865475f));
                v3 = 0.5f * v3 * (1.0f + erff(v3 * 0.7071067811865475f));
                __nv_bfloat162 hh, ll;
                hh.x = __float2bfloat16(v0); hh.y = __float2bfloat16(v1);
                ll.x = __float2bfloat16(v0 - __bfloat162float(hh.x));
                ll.y = __float2bfloat16(v1 - __bfloat162float(hh.y));
                *(__nv_bfloat162*)&Chi[(size_t)row0 * N + col] = hh;
                *(__nv_bfloat162*)&Clo[(size_t)row0 * N + col] = ll;
                hh.x = __float2bfloat16(v2); hh.y = __float2bfloat16(v3);
                ll.x = __float2bfloat16(v2 - __bfloat162float(hh.x));
                ll.y = __float2bfloat16(v3 - __bfloat162float(hh.y));
                *(__nv_bfloat162*)&Chi[(size_t)(row0 + 8) * N + col] = hh;
                *(__nv_bfloat162*)&Clo[(size_t)(row0 + 8) * N + col] = ll;
            }
        }
    }
}

// ---------------------------------------------------------------------------
// fused attention: one CTA per batch-head; writes o as bf16 hi/lo
// ---------------------------------------------------------------------------
__global__ __launch_bounds__(256) void attn_kernel(int use_prev)
{
    int bh = blockIdx.x;
    int bc = bh >> 4, h = bh & 15;

    __shared__ float Ks[TOTAL_S][17];
    __shared__ float Vs[TOTAL_S][17];
    int tid = threadIdx.x;
    for (int i = tid; i < TOTAL_S * DK; i += 256) {
        int s = i >> 4, d = i & 15;
        size_t gi = (size_t)(bc * TOTAL_S + s) * 768 + (h << 4) + d;
        Ks[s][d] = g_qkv[gi + 256];
        Vs[s][d] = g_qkv[gi + 512];
    }
    __syncthreads();

    int warp = tid >> 5, lane = tid & 31;
    for (int it = 0; it < 40; it++) {
        int qi = warp * 40 + it;
        const float* qp = &g_qkv[(size_t)(bc * TOTAL_S + qi) * 768 + (h << 4)];
        float qv[DK];
#pragma unroll
        for (int d = 0; d < DK; d++) qv[d] = qp[d];

        float* srow = &g_scores[((size_t)bh * TOTAL_S + qi) * TOTAL_S];
        float sc[10];
#pragma unroll
        for (int j = 0; j < 10; j++) {
            int kk = j * 32 + lane;
            float acc = 0.f;
#pragma unroll
            for (int d = 0; d < DK; d++) acc += qv[d] * Ks[kk][d];
            acc *= ATTN_SCALE;
            if (use_prev) acc += srow[kk];
            sc[j] = acc;
            srow[kk] = acc;
        }
        float m = sc[0];
#pragma unroll
        for (int j = 1; j < 10; j++) m = fmaxf(m, sc[j]);
#pragma unroll
        for (int o = 16; o; o >>= 1) m = fmaxf(m, __shfl_xor_sync(0xffffffffu, m, o));
        float sum = 0.f;
#pragma unroll
        for (int j = 0; j < 10; j++) { sc[j] = __expf(sc[j] - m); sum += sc[j]; }
#pragma unroll
        for (int o = 16; o; o >>= 1) sum += __shfl_xor_sync(0xffffffffu, sum, o);
        float inv = 1.f / sum;

        float oacc[DK];
#pragma unroll
        for (int d = 0; d < DK; d++) oacc[d] = 0.f;
#pragma unroll
        for (int j = 0; j < 10; j++) {
            int kk = j * 32 + lane;
            float wgt = sc[j] * inv;
#pragma unroll
            for (int d = 0; d < DK; d++) oacc[d] += wgt * Vs[kk][d];
        }
#pragma unroll
        for (int d = 0; d < DK; d++) {
#pragma unroll
            for (int o = 16; o; o >>= 1)
                oacc[d] += __shfl_xor_sync(0xffffffffu, oacc[d], o);
        }
        if (lane < DK) {
            float val = oacc[lane];
            size_t oi = (size_t)(bc * TOTAL_S + qi) * D_MODEL + (h << 4) + lane;
            __nv_bfloat16 hh = __float2bfloat16(val);
            g_o_hi[oi] = hh;
            g_o_lo[oi] = __float2bfloat16(val - __bfloat162float(hh));
        }
    }
}

// ---------------------------------------------------------------------------
__global__ __launch_bounds__(256) void resid_ln_kernel(
    const float* __restrict__ delta,
    const float* __restrict__ gs, const float* __restrict__ gb)
{
    int row = blockIdx.x;
    int d = threadIdx.x;
    int warp = d >> 5, lane = d & 31;
    size_t idx = (size_t)row * D_MODEL + d;
    float t = g_u[idx] + delta[idx];

    __shared__ float sred[8];
    float ws = t;
#pragma unroll
    for (int o = 16; o; o >>= 1) ws += __shfl_xor_sync(0xffffffffu, ws, o);
    if (lane == 0) sred[warp] = ws;
    __syncthreads();
    float tot = 0.f;
#pragma unroll
    for (int i = 0; i < 8; i++) tot += sred[i];
    float mean = tot * (1.0f / D_MODEL);
    __syncthreads();

    float df = t - mean;
    ws = df * df;
#pragma unroll
    for (int o = 16; o; o >>= 1) ws += __shfl_xor_sync(0xffffffffu, ws, o);
    if (lane == 0) sred[warp] = ws;
    __syncthreads();
    tot = 0.f;
#pragma unroll
    for (int i = 0; i < 8; i++) tot += sred[i];
    float var = tot * (1.0f / D_MODEL);

    float y = df * rsqrtf(var + LN_EPS) * gs[d] + gb[d];
    g_u[idx] = y;
    __nv_bfloat16 h = __float2bfloat16(y);
    g_u_hi[idx] = h;
    g_u_lo[idx] = __float2bfloat16(y - __bfloat162float(h));
}

// ---------------------------------------------------------------------------
__global__ __launch_bounds__(96) void head_partial_kernel(const float* __restrict__ Wh)
{
    int d = blockIdx.x;
    int t = threadIdx.x;
    __shared__ float usm[BROWS][TOTAL_S];
    for (int i = t; i < BROWS * TOTAL_S; i += 96) {
        int bcc = i / TOTAL_S, s = i % TOTAL_S;
        usm[bcc][s] = g_u[(size_t)(bcc * TOTAL_S + s) * D_MODEL + d];
    }
    __syncthreads();
    float acc[BROWS];
#pragma unroll
    for (int b = 0; b < BROWS; b++) acc[b] = 0.f;
    for (int s = 0; s < TOTAL_S; s++) {
        float w = Wh[((size_t)d * TOTAL_S + s) * TGT + t];
#pragma unroll
        for (int b = 0; b < BROWS; b++) acc[b] += usm[b][s] * w;
    }
#pragma unroll
    for (int b = 0; b < BROWS; b++)
        g_part[((size_t)d * BROWS + b) * TGT + t] = acc[b];
}

__global__ __launch_bounds__(256) void head_reduce_kernel(
    const float* __restrict__ bh,
    const float* __restrict__ revin_w, const float* __restrict__ revin_b,
    float* __restrict__ out)
{
    int idx = blockIdx.x * blockDim.x + threadIdx.x;
    if (idx >= BROWS * TGT) return;
    int bcc = idx / TGT, t = idx % TGT;
    float acc = 0.f;
    for (int d = 0; d < D_MODEL; d++)
        acc += g_part[((size_t)d * BROWS + bcc) * TGT + t];
    acc += bh[t];
    int c = bcc & 7;
    out[idx] = (acc - revin_b[c]) / (revin_w[c] + 1e-10f) * g_std[bcc] + g_mean[bcc];
}

// ---------------------------------------------------------------------------
extern "C" void kernel_launch(void* const* d_in, const int* in_sizes, int n_in,
                              void* d_out, int out_size)
{
    const float* z       = (const float*)d_in[0];
    const float* revin_w = (const float*)d_in[1];
    const float* revin_b = (const float*)d_in[2];
    const float* Wf      = (const float*)d_in[3];
    const float* bf      = (const float*)d_in[4];
    const float* Wc      = (const float*)d_in[5];
    const float* bcoarse = (const float*)d_in[6];
    const float* Wpos    = (const float*)d_in[7];
    const float* WQ      = (const float*)d_in[8];
    const float* bQ      = (const float*)d_in[9];
    const float* WK      = (const float*)d_in[10];
    const float* bK      = (const float*)d_in[11];
    const float* WV      = (const float*)d_in[12];
    const float* bV      = (const float*)d_in[13];
    const float* WO      = (const float*)d_in[14];
    const float* bO      = (const float*)d_in[15];
    const float* ln1_s   = (const float*)d_in[16];
    const float* ln1_b   = (const float*)d_in[17];
    const float* ln2_s   = (const float*)d_in[18];
    const float* ln2_b   = (const float*)d_in[19];
    const float* F1      = (const float*)d_in[20];
    const float* c1      = (const float*)d_in[21];
    const float* F2      = (const float*)d_in[22];
    const float* c2      = (const float*)d_in[23];
    const float* Wh      = (const float*)d_in[24];
    const float* bh      = (const float*)d_in[25];
    float* out = (float*)d_out;

    float *u, *qkv, *tmp, *bqkv;
    __nv_bfloat16 *uh, *ul, *oh, *ol, *h1h, *h1l, *wth, *wtl;
    cudaGetSymbolAddress((void**)&u,    g_u);
    cudaGetSymbolAddress((void**)&qkv,  g_qkv);
    cudaGetSymbolAddress((void**)&tmp,  g_tmp);
    cudaGetSymbolAddress((void**)&bqkv, g_bqkv);
    cudaGetSymbolAddress((void**)&uh,   g_u_hi);
    cudaGetSymbolAddress((void**)&ul,   g_u_lo);
    cudaGetSymbolAddress((void**)&oh,   g_o_hi);
    cudaGetSymbolAddress((void**)&ol,   g_o_lo);
    cudaGetSymbolAddress((void**)&h1h,  g_h1_hi);
    cudaGetSymbolAddress((void**)&h1l,  g_h1_lo);
    cudaGetSymbolAddress((void**)&wth,  g_wt_hi);
    cudaGetSymbolAddress((void**)&wtl,  g_wt_lo);

    const int SMEM128 = 2 * (2 * 128 * ASTRIDE * 2 + 2 * 128 * ASTRIDE * 2);
    const int SMEM64  = 2 * (2 * 64  * ASTRIDE * 2 + 2 * 128 * ASTRIDE * 2);
    cudaFuncSetAttribute(gemm_tc<0,128>, cudaFuncAttributeMaxDynamicSharedMemorySize, SMEM128);
    cudaFuncSetAttribute(gemm_tc<1,128>, cudaFuncAttributeMaxDynamicSharedMemorySize, SMEM128);
    cudaFuncSetAttribute(gemm_tc<0,64>,  cudaFuncAttributeMaxDynamicSharedMemorySize, SMEM64);

    wsplitT_kernel<<<dim3(8, 8, NLAYERS), 256>>>(WQ, wth + WOFF_Q,  wtl + WOFF_Q,  256, 256, 65536, WSTRIDE);
    wsplitT_kernel<<<dim3(8, 8, NLAYERS), 256>>>(WK, wth + WOFF_K,  wtl + WOFF_K,  256, 256, 65536, WSTRIDE);
    wsplitT_kernel<<<dim3(8, 8, NLAYERS), 256>>>(WV, wth + WOFF_V,  wtl + WOFF_V,  256, 256, 65536, WSTRIDE);
    wsplitT_kernel<<<dim3(8, 8, NLAYERS), 256>>>(WO, wth + WOFF_O,  wtl + WOFF_O,  256, 256, 65536, WSTRIDE);
    wsplitT_kernel<<<dim3(32, 8, NLAYERS), 256>>>(F1, wth + WOFF_F1, wtl + WOFF_F1, 256, 1024, 262144, WSTRIDE);
    wsplitT_kernel<<<dim3(8, 32, NLAYERS), 256>>>(F2, wth + WOFF_F2, wtl + WOFF_F2, 1024, 256, 262144, WSTRIDE);
    biaspack_kernel<<<(NLAYERS * 768 + 255) / 256, 256>>>(bQ, bK, bV);

    stats_kernel<<<BROWS, 256>>>(z);
    embed_kernel<<<dim3(TOTAL_S, BROWS), 256>>>(z, revin_w, revin_b,
                                                Wf, bf, Wc, bcoarse, Wpos);

    for (int l = 0; l < NLAYERS; l++) {
        const size_t L = (size_t)l * WSTRIDE;
        gemm_tc<0,128><<<dim3(6, 40), 256, SMEM128>>>(
            uh, ul, wth + L + WOFF_Q, wtl + L + WOFF_Q,
            bqkv + l * 768, qkv, nullptr, nullptr, 768, D_MODEL);
        attn_kernel<<<BROWS * NHEADS, 256>>>(l > 0 ? 1 : 0);
        gemm_tc<0,64><<<dim3(2, 80), 256, SMEM64>>>(
            oh, ol, wth + L + WOFF_O, wtl + L + WOFF_O,
            bO + l * D_MODEL, tmp, nullptr, nullptr, D_MODEL, D_MODEL);
        resid_ln_kernel<<<SEQ, 256>>>(tmp, ln1_s + l * D_MODEL, ln1_b + l * D_MODEL);
        gemm_tc<1,128><<<dim3(8, 40), 256, SMEM128>>>(
            uh, ul, wth + L + WOFF_F1, wtl + L + WOFF_F1,
            c1 + l * DFF, nullptr, h1h, h1l, DFF, D_MODEL);
        gemm_tc<0,64><<<dim3(2, 80), 256, SMEM64>>>(
            h1h, h1l, wth + L + WOFF_F2, wtl + L + WOFF_F2,
            c2 + l * D_MODEL, tmp, nullptr, nullptr, D_MODEL, DFF);
        resid_ln_kernel<<<SEQ, 256>>>(tmp, ln2_s + l * D_MODEL, ln2_b + l * D_MODEL);
    }

    head_partial_kernel<<<D_MODEL, 96>>>(Wh);
    head_reduce_kernel<<<6, 256>>>(bh, revin_w, revin_b, out);
}

// round 5
// speedup vs baseline: 1.5188x; 1.0089x over previous
#include <cuda_runtime.h>
#include <cuda_bf16.h>
#include <math.h>
#include <stdint.h>

#define CTX      1024
#define BROWS    16
#define TOTAL_S  320
#define NF       256
#define D_MODEL  256
#define NHEADS   16
#define DK       16
#define DFF      1024
#define NLAYERS  4
#define TGT      96
#define SEQ      (BROWS * TOTAL_S)   // 5120
#define ATTN_SCALE 0.25f
#define LN_EPS   1e-5f

// ---------------------------------------------------------------------------
// warp MMA + cp.async helpers (sm_80+ path; tcgen05 unavailable at sm_103)
// ---------------------------------------------------------------------------
__device__ __forceinline__ uint32_t smem_u32(const void* p) {
    uint32_t a;
    asm("{ .reg .u64 t; cvta.to.shared.u64 t, %1; cvt.u32.u64 %0, t; }"
        : "=r"(a) : "l"(p));
    return a;
}
__device__ __forceinline__ void ldsm_x4(uint32_t& r0, uint32_t& r1,
                                        uint32_t& r2, uint32_t& r3, uint32_t addr) {
    asm volatile("ldmatrix.sync.aligned.m8n8.x4.shared.b16 {%0,%1,%2,%3}, [%4];"
                 : "=r"(r0), "=r"(r1), "=r"(r2), "=r"(r3) : "r"(addr));
}
__device__ __forceinline__ void mma_bf16(float* c, const uint32_t* a, const uint32_t* b) {
    asm volatile(
        "mma.sync.aligned.m16n8k16.row.col.f32.bf16.bf16.f32 "
        "{%0,%1,%2,%3}, {%4,%5,%6,%7}, {%8,%9}, {%0,%1,%2,%3};"
        : "+f"(c[0]), "+f"(c[1]), "+f"(c[2]), "+f"(c[3])
        : "r"(a[0]), "r"(a[1]), "r"(a[2]), "r"(a[3]), "r"(b[0]), "r"(b[1]));
}
#define CP_ASYNC16(dst, src) \
    asm volatile("cp.async.cg.shared.global [%0], [%1], 16;" :: "r"(dst), "l"(src))
#define CP_COMMIT() asm volatile("cp.async.commit_group;" ::: "memory")
#define CP_WAIT0()  asm volatile("cp.async.wait_group 0;" ::: "memory")

// ---------------------------------------------------------------------------
// scratch
// ---------------------------------------------------------------------------
__device__ __align__(256) float g_u[SEQ * D_MODEL];
__device__ __align__(256) float g_qkv[SEQ * 768];
__device__ __align__(256) float g_tmp[SEQ * D_MODEL];
__device__ __align__(256) float g_scores[BROWS * NHEADS * TOTAL_S * TOTAL_S];
__device__ float g_mean[BROWS];
__device__ float g_std[BROWS];
__device__ __align__(256) float g_part[D_MODEL * BROWS * TGT];
__device__ __align__(256) float g_bqkv[NLAYERS * 768];

__device__ __align__(256) __nv_bfloat16 g_u_hi[SEQ * D_MODEL];
__device__ __align__(256) __nv_bfloat16 g_u_lo[SEQ * D_MODEL];
__device__ __align__(256) __nv_bfloat16 g_o_hi[SEQ * D_MODEL];
__device__ __align__(256) __nv_bfloat16 g_o_lo[SEQ * D_MODEL];
__device__ __align__(256) __nv_bfloat16 g_h1_hi[SEQ * DFF];
__device__ __align__(256) __nv_bfloat16 g_h1_lo[SEQ * DFF];
#define WOFF_Q   0
#define WOFF_K   65536
#define WOFF_V   131072
#define WOFF_O   196608
#define WOFF_F1  262144
#define WOFF_F2  524288
#define WSTRIDE  786432
__device__ __align__(256) __nv_bfloat16 g_wt_hi[NLAYERS * WSTRIDE];
__device__ __align__(256) __nv_bfloat16 g_wt_lo[NLAYERS * WSTRIDE];

// ---------------------------------------------------------------------------
// merged weight transpose + split (all 6 matrices x 4 layers, one launch)
// grid: (256 tiles, 6 kinds, 4 layers)
// ---------------------------------------------------------------------------
__global__ __launch_bounds__(256) void wsplit_all_kernel(
    const float* __restrict__ WQ, const float* __restrict__ WK,
    const float* __restrict__ WV, const float* __restrict__ WO,
    const float* __restrict__ F1, const float* __restrict__ F2)
{
    int kind = blockIdx.y, l = blockIdx.z, tile = blockIdx.x;
    const float* W; int R, C; size_t inl, ooff;
    switch (kind) {
        case 0: W = WQ; R = 256;  C = 256;  inl = 65536;  ooff = WOFF_Q;  break;
        case 1: W = WK; R = 256;  C = 256;  inl = 65536;  ooff = WOFF_K;  break;
        case 2: W = WV; R = 256;  C = 256;  inl = 65536;  ooff = WOFF_V;  break;
        case 3: W = WO; R = 256;  C = 256;  inl = 65536;  ooff = WOFF_O;  break;
        case 4: W = F1; R = 256;  C = 1024; inl = 262144; ooff = WOFF_F1; break;
        default: W = F2; R = 1024; C = 256; inl = 262144; ooff = WOFF_F2; break;
    }
    int ct = C >> 5, rt = R >> 5;
    if (tile >= ct * rt) return;
    int c0 = (tile % ct) << 5, r0 = (tile / ct) << 5;
    const float* Wl = W + (size_t)l * inl;

    __shared__ float t[32][33];
    int tx = threadIdx.x & 31, ty = threadIdx.x >> 5;
#pragma unroll
    for (int i = 0; i < 32; i += 8)
        t[ty + i][tx] = Wl[(size_t)(r0 + ty + i) * C + c0 + tx];
    __syncthreads();
#pragma unroll
    for (int i = 0; i < 32; i += 8) {
        float x = t[tx][ty + i];
        size_t oi = (size_t)l * WSTRIDE + ooff + (size_t)(c0 + ty + i) * R + (r0 + tx);
        __nv_bfloat16 h = __float2bfloat16(x);
        g_wt_hi[oi] = h;
        g_wt_lo[oi] = __float2bfloat16(x - __bfloat162float(h));
    }
}

__global__ __launch_bounds__(256) void biaspack_kernel(
    const float* __restrict__ bQ, const float* __restrict__ bK,
    const float* __restrict__ bV)
{
    int i = blockIdx.x * 256 + threadIdx.x;
    if (i >= NLAYERS * 768) return;
    int l = i / 768, j = i % 768;
    float v = (j < 256) ? bQ[l * 256 + j]
            : (j < 512) ? bK[l * 256 + j - 256]
                        : bV[l * 256 + j - 512];
    g_bqkv[i] = v;
}

// ---------------------------------------------------------------------------
__global__ __launch_bounds__(256) void stats_kernel(const float* __restrict__ z) {
    int r = blockIdx.x;
    int tid = threadIdx.x;
    float s = 0.f, s2 = 0.f;
    for (int i = tid; i < CTX; i += 256) {
        float v = z[r * CTX + i];
        s += v; s2 += v * v;
    }
    __shared__ float rs[256], rq[256];
    rs[tid] = s; rq[tid] = s2;
    __syncthreads();
    for (int o = 128; o; o >>= 1) {
        if (tid < o) { rs[tid] += rs[tid + o]; rq[tid] += rq[tid + o]; }
        __syncthreads();
    }
    if (tid == 0) {
        float m = rs[0] / CTX;
        float var = rq[0] / CTX - m * m;
        g_mean[r] = m;
        g_std[r]  = sqrtf(var + LN_EPS);
    }
}

// ---------------------------------------------------------------------------
__global__ __launch_bounds__(256) void embed_kernel(
    const float* __restrict__ z,
    const float* __restrict__ revin_w, const float* __restrict__ revin_b,
    const float* __restrict__ Wf, const float* __restrict__ bf,
    const float* __restrict__ Wc, const float* __restrict__ bcoarse,
    const float* __restrict__ Wpos)
{
    int bch = blockIdx.y;
    int s   = blockIdx.x;
    int d   = threadIdx.x;
    int c   = bch & 7;

    __shared__ float patch[32];
    int plen, stride, p;
    const float* W; const float* bias;
    if (s < NF) { plen = 8;  stride = 4;  p = s;      W = Wf; bias = bf; }
    else        { plen = 32; stride = 16; p = s - NF; W = Wc; bias = bcoarse; }

    if (d < plen) {
        int t = p * stride + d;
        if (t > CTX - 1) t = CTX - 1;
        float zv = z[bch * CTX + t];
        patch[d] = (zv - g_mean[bch]) / g_std[bch] * revin_w[c] + revin_b[c];
    }
    __syncthreads();

    float acc = bias[d] + Wpos[s * D_MODEL + d];
    for (int i = 0; i < plen; i++) acc += patch[i] * W[i * D_MODEL + d];
    size_t idx = (size_t)(bch * TOTAL_S + s) * D_MODEL + d;
    g_u[idx] = acc;
    __nv_bfloat16 h = __float2bfloat16(acc);
    g_u_hi[idx] = h;
    g_u_lo[idx] = __float2bfloat16(acc - __bfloat162float(h));
}

// ---------------------------------------------------------------------------
// HMMA bf16x3 GEMM, cp.async 2-stage pipeline. MT = CTA M-tile (64|128).
// ---------------------------------------------------------------------------
#define ASTRIDE 72

template<int EPI, int MT>
__global__ __launch_bounds__(256) void gemm_tc(
    const __nv_bfloat16* __restrict__ Ah, const __nv_bfloat16* __restrict__ Al,
    const __nv_bfloat16* __restrict__ Bh, const __nv_bfloat16* __restrict__ Bl,
    const float* __restrict__ bias,
    float* __restrict__ Cf,
    __nv_bfloat16* __restrict__ Chi, __nv_bfloat16* __restrict__ Clo,
    int N, int K)
{
    constexpr int WNs = (MT == 128) ? 2 : 4;
    constexpr int NT  = 16 / WNs;
    constexpr int BUF_A = MT * ASTRIDE * 2;
    constexpr int BUF_B = 128 * ASTRIDE * 2;
    constexpr int STAGE = 2 * BUF_A + 2 * BUF_B;

    extern __shared__ char smem[];
    const uint32_t sbase = smem_u32(smem);

    const int tid = threadIdx.x;
    const int bm = blockIdx.y * MT, bn = blockIdx.x * 128;
    const int warp = tid >> 5, lane = tid & 31;
    const int wm = warp / WNs, wn = warp % WNs;

    const int sr = tid >> 3, sc = (tid & 7) * 8;

    float acc[2][NT][4];
#pragma unroll
    for (int mt = 0; mt < 2; mt++)
#pragma unroll
        for (int nt = 0; nt < NT; nt++)
#pragma unroll
            for (int i = 0; i < 4; i++) acc[mt][nt][i] = 0.f;

    const int gg = lane >> 3, l7 = lane & 7;
    const int a_row = (gg & 1) * 8 + l7;
    const int a_kb  = (gg >> 1) * 16;
    const int b_row = (gg >> 1) * 8 + l7;
    const int b_kb  = (gg & 1) * 16;

    const int nchunk = K >> 6;

#define STAGE_LOAD(kc, s) do { \
        const int _k0 = (kc) << 6; \
        uint32_t _base = sbase + (s) * STAGE; \
        _Pragma("unroll") \
        for (int i = 0; i < MT / 32; i++) { \
            int r = sr + i * 32; \
            uint32_t so = _base + r * 144 + sc * 2; \
            CP_ASYNC16(so, Ah + (size_t)(bm + r) * K + _k0 + sc); \
            CP_ASYNC16(so + BUF_A, Al + (size_t)(bm + r) * K + _k0 + sc); \
        } \
        _Pragma("unroll") \
        for (int i = 0; i < 4; i++) { \
            int r = sr + i * 32; \
            uint32_t so = _base + 2 * BUF_A + r * 144 + sc * 2; \
            CP_ASYNC16(so, Bh + (size_t)(bn + r) * K + _k0 + sc); \
            CP_ASYNC16(so + BUF_B, Bl + (size_t)(bn + r) * K + _k0 + sc); \
        } \
        CP_COMMIT(); \
    } while (0)

    STAGE_LOAD(0, 0);

    for (int kc = 0; kc < nchunk; kc++) {
        CP_WAIT0();
        __syncthreads();
        if (kc + 1 < nchunk) STAGE_LOAD(kc + 1, (kc + 1) & 1);

        const uint32_t base = sbase + (kc & 1) * STAGE;
        const uint32_t uAh = base, uAl = base + BUF_A;
        const uint32_t uBh = base + 2 * BUF_A, uBl = uBh + BUF_B;

#pragma unroll
        for (int ks = 0; ks < 4; ks++) {
            uint32_t ah[2][4], al[2][4], bh[NT][2], bl[NT][2];
#pragma unroll
            for (int mt = 0; mt < 2; mt++) {
                int row = wm * 32 + mt * 16 + a_row;
                uint32_t off = (uint32_t)(row * 144 + ks * 32 + a_kb);
                ldsm_x4(ah[mt][0], ah[mt][1], ah[mt][2], ah[mt][3], uAh + off);
                ldsm_x4(al[mt][0], al[mt][1], al[mt][2], al[mt][3], uAl + off);
            }
#pragma unroll
            for (int j = 0; j < NT / 2; j++) {
                int row = wn * (128 / WNs) + j * 16 + b_row;
                uint32_t off = (uint32_t)(row * 144 + ks * 32 + b_kb);
                uint32_t r0, r1, r2, r3;
                ldsm_x4(r0, r1, r2, r3, uBh + off);
                bh[2 * j][0] = r0; bh[2 * j][1] = r1;
                bh[2 * j + 1][0] = r2; bh[2 * j + 1][1] = r3;
                ldsm_x4(r0, r1, r2, r3, uBl + off);
                bl[2 * j][0] = r0; bl[2 * j][1] = r1;
                bl[2 * j + 1][0] = r2; bl[2 * j + 1][1] = r3;
            }
#pragma unroll
            for (int mt = 0; mt < 2; mt++)
#pragma unroll
                for (int nt = 0; nt < NT; nt++) {
                    mma_bf16(acc[mt][nt], ah[mt], bh[nt]);
                    mma_bf16(acc[mt][nt], ah[mt], bl[nt]);
                    mma_bf16(acc[mt][nt], al[mt], bh[nt]);
                }
        }
        __syncthreads();
    }
#undef STAGE_LOAD

#pragma unroll
    for (int mt = 0; mt < 2; mt++) {
        int row0 = bm + wm * 32 + mt * 16 + (lane >> 2);
#pragma unroll
        for (int nt = 0; nt < NT; nt++) {
            int col = bn + wn * (128 / WNs) + nt * 8 + (lane & 3) * 2;
            float b0 = bias[col], b1 = bias[col + 1];
            float v0 = acc[mt][nt][0] + b0, v1 = acc[mt][nt][1] + b1;
            float v2 = acc[mt][nt][2] + b0, v3 = acc[mt][nt][3] + b1;
            if (EPI == 0) {
                float2 p0 = {v0, v1}, p1 = {v2, v3};
                *(float2*)&Cf[(size_t)row0 * N + col] = p0;
                *(float2*)&Cf[(size_t)(row0 + 8) * N + col] = p1;
            } else {
                v0 = 0.5f * v0 * (1.0f + erff(v0 * 0.7071067811865475f));
                v1 = 0.5f * v1 * (1.0f + erff(v1 * 0.7071067811865475f));
                v2 = 0.5f * v2 * (1.0f + erff(v2 * 0.7071067811865475f));
                v3 = 0.5f * v3 * (1.0f + erff(v3 * 0.7071067811865475f));
                __nv_bfloat162 hh, ll;
                hh.x = __float2bfloat16(v0); hh.y = __float2bfloat16(v1);
                ll.x = __float2bfloat16(v0 - __bfloat162float(hh.x));
                ll.y = __float2bfloat16(v1 - __bfloat162float(hh.y));
                *(__nv_bfloat162*)&Chi[(size_t)row0 * N + col] = hh;
                *(__nv_bfloat162*)&Clo[(size_t)row0 * N + col] = ll;
                hh.x = __float2bfloat16(v2); hh.y = __float2bfloat16(v3);
                ll.x = __float2bfloat16(v2 - __bfloat162float(hh.x));
                ll.y = __float2bfloat16(v3 - __bfloat162float(hh.y));
                *(__nv_bfloat162*)&Chi[(size_t)(row0 + 8) * N + col] = hh;
                *(__nv_bfloat162*)&Clo[(size_t)(row0 + 8) * N + col] = ll;
            }
        }
    }
}

// ---------------------------------------------------------------------------
// fused attention: one CTA per batch-head; Q/K/V staged in dynamic smem;
// writes o as bf16 hi/lo; score write skipped on last layer.
// ---------------------------------------------------------------------------
#define ATTN_SMEM (3 * TOTAL_S * 17 * 4)

__global__ __launch_bounds__(256) void attn_kernel(int use_prev, int wr)
{
    extern __shared__ float asmem[];
    float* Ks = asmem;                     // [320][17]
    float* Vs = Ks + TOTAL_S * 17;
    float* Qs = Vs + TOTAL_S * 17;

    int bh = blockIdx.x;
    int bc = bh >> 4, h = bh & 15;

    int tid = threadIdx.x;
    for (int i = tid; i < TOTAL_S * DK; i += 256) {
        int s = i >> 4, d = i & 15;
        size_t gi = (size_t)(bc * TOTAL_S + s) * 768 + (h << 4) + d;
        Qs[s * 17 + d] = g_qkv[gi];
        Ks[s * 17 + d] = g_qkv[gi + 256];
        Vs[s * 17 + d] = g_qkv[gi + 512];
    }
    __syncthreads();

    int warp = tid >> 5, lane = tid & 31;
    for (int it = 0; it < 40; it++) {
        int qi = warp * 40 + it;
        float qv[DK];
#pragma unroll
        for (int d = 0; d < DK; d++) qv[d] = Qs[qi * 17 + d];

        float* srow = &g_scores[((size_t)bh * TOTAL_S + qi) * TOTAL_S];
        float sc[10];
#pragma unroll
        for (int j = 0; j < 10; j++) {
            int kk = j * 32 + lane;
            float acc = 0.f;
#pragma unroll
            for (int d = 0; d < DK; d++) acc += qv[d] * Ks[kk * 17 + d];
            acc *= ATTN_SCALE;
            if (use_prev) acc += srow[kk];
            sc[j] = acc;
            if (wr) srow[kk] = acc;
        }
        float m = sc[0];
#pragma unroll
        for (int j = 1; j < 10; j++) m = fmaxf(m, sc[j]);
#pragma unroll
        for (int o = 16; o; o >>= 1) m = fmaxf(m, __shfl_xor_sync(0xffffffffu, m, o));
        float sum = 0.f;
#pragma unroll
        for (int j = 0; j < 10; j++) { sc[j] = __expf(sc[j] - m); sum += sc[j]; }
#pragma unroll
        for (int o = 16; o; o >>= 1) sum += __shfl_xor_sync(0xffffffffu, sum, o);
        float inv = 1.f / sum;

        float oacc[DK];
#pragma unroll
        for (int d = 0; d < DK; d++) oacc[d] = 0.f;
#pragma unroll
        for (int j = 0; j < 10; j++) {
            int kk = j * 32 + lane;
            float wgt = sc[j] * inv;
#pragma unroll
            for (int d = 0; d < DK; d++) oacc[d] += wgt * Vs[kk * 17 + d];
        }
#pragma unroll
        for (int d = 0; d < DK; d++) {
#pragma unroll
            for (int o = 16; o; o >>= 1)
                oacc[d] += __shfl_xor_sync(0xffffffffu, oacc[d], o);
        }
        if (lane < DK) {
            float val = oacc[lane];
            size_t oi = (size_t)(bc * TOTAL_S + qi) * D_MODEL + (h << 4) + lane;
            __nv_bfloat16 hh = __float2bfloat16(val);
            g_o_hi[oi] = hh;
            g_o_lo[oi] = __float2bfloat16(val - __bfloat162float(hh));
        }
    }
}

// ---------------------------------------------------------------------------
__global__ __launch_bounds__(256) void resid_ln_kernel(
    const float* __restrict__ delta,
    const float* __restrict__ gs, const float* __restrict__ gb)
{
    int row = blockIdx.x;
    int d = threadIdx.x;
    int warp = d >> 5, lane = d & 31;
    size_t idx = (size_t)row * D_MODEL + d;
    float t = g_u[idx] + delta[idx];

    __shared__ float sred[8];
    float ws = t;
#pragma unroll
    for (int o = 16; o; o >>= 1) ws += __shfl_xor_sync(0xffffffffu, ws, o);
    if (lane == 0) sred[warp] = ws;
    __syncthreads();
    float tot = 0.f;
#pragma unroll
    for (int i = 0; i < 8; i++) tot += sred[i];
    float mean = tot * (1.0f / D_MODEL);
    __syncthreads();

    float df = t - mean;
    ws = df * df;
#pragma unroll
    for (int o = 16; o; o >>= 1) ws += __shfl_xor_sync(0xffffffffu, ws, o);
    if (lane == 0) sred[warp] = ws;
    __syncthreads();
    tot = 0.f;
#pragma unroll
    for (int i = 0; i < 8; i++) tot += sred[i];
    float var = tot * (1.0f / D_MODEL);

    float y = df * rsqrtf(var + LN_EPS) * gs[d] + gb[d];
    g_u[idx] = y;
    __nv_bfloat16 h = __float2bfloat16(y);
    g_u_hi[idx] = h;
    g_u_lo[idx] = __float2bfloat16(y - __bfloat162float(h));
}

// ---------------------------------------------------------------------------
__global__ __launch_bounds__(96) void head_partial_kernel(const float* __restrict__ Wh)
{
    int d = blockIdx.x;
    int t = threadIdx.x;
    __shared__ float usm[BROWS][TOTAL_S];
    for (int i = t; i < BROWS * TOTAL_S; i += 96) {
        int bcc = i / TOTAL_S, s = i % TOTAL_S;
        usm[bcc][s] = g_u[(size_t)(bcc * TOTAL_S + s) * D_MODEL + d];
    }
    __syncthreads();
    float acc[BROWS];
#pragma unroll
    for (int b = 0; b < BROWS; b++) acc[b] = 0.f;
    for (int s = 0; s < TOTAL_S; s++) {
        float w = Wh[((size_t)d * TOTAL_S + s) * TGT + t];
#pragma unroll
        for (int b = 0; b < BROWS; b++) acc[b] += usm[b][s] * w;
    }
#pragma unroll
    for (int b = 0; b < BROWS; b++)
        g_part[((size_t)d * BROWS + b) * TGT + t] = acc[b];
}

__global__ __launch_bounds__(256) void head_reduce_kernel(
    const float* __restrict__ bh,
    const float* __restrict__ revin_w, const float* __restrict__ revin_b,
    float* __restrict__ out)
{
    int idx = blockIdx.x * blockDim.x + threadIdx.x;
    if (idx >= BROWS * TGT) return;
    int bcc = idx / TGT, t = idx % TGT;
    float acc = 0.f;
    for (int d = 0; d < D_MODEL; d++)
        acc += g_part[((size_t)d * BROWS + bcc) * TGT + t];
    acc += bh[t];
    int c = bcc & 7;
    out[idx] = (acc - revin_b[c]) / (revin_w[c] + 1e-10f) * g_std[bcc] + g_mean[bcc];
}

// ---------------------------------------------------------------------------
extern "C" void kernel_launch(void* const* d_in, const int* in_sizes, int n_in,
                              void* d_out, int out_size)
{
    const float* z       = (const float*)d_in[0];
    const float* revin_w = (const float*)d_in[1];
    const float* revin_b = (const float*)d_in[2];
    const float* Wf      = (const float*)d_in[3];
    const float* bf      = (const float*)d_in[4];
    const float* Wc      = (const float*)d_in[5];
    const float* bcoarse = (const float*)d_in[6];
    const float* Wpos    = (const float*)d_in[7];
    const float* WQ      = (const float*)d_in[8];
    const float* bQ      = (const float*)d_in[9];
    const float* WK      = (const float*)d_in[10];
    const float* bK      = (const float*)d_in[11];
    const float* WV      = (const float*)d_in[12];
    const float* bV      = (const float*)d_in[13];
    const float* WO      = (const float*)d_in[14];
    const float* bO      = (const float*)d_in[15];
    const float* ln1_s   = (const float*)d_in[16];
    const float* ln1_b   = (const float*)d_in[17];
    const float* ln2_s   = (const float*)d_in[18];
    const float* ln2_b   = (const float*)d_in[19];
    const float* F1      = (const float*)d_in[20];
    const float* c1      = (const float*)d_in[21];
    const float* F2      = (const float*)d_in[22];
    const float* c2      = (const float*)d_in[23];
    const float* Wh      = (const float*)d_in[24];
    const float* bh      = (const float*)d_in[25];
    float* out = (float*)d_out;

    float *u, *qkv, *tmp, *bqkv;
    __nv_bfloat16 *uh, *ul, *oh, *ol, *h1h, *h1l, *wth, *wtl;
    cudaGetSymbolAddress((void**)&u,    g_u);
    cudaGetSymbolAddress((void**)&qkv,  g_qkv);
    cudaGetSymbolAddress((void**)&tmp,  g_tmp);
    cudaGetSymbolAddress((void**)&bqkv, g_bqkv);
    cudaGetSymbolAddress((void**)&uh,   g_u_hi);
    cudaGetSymbolAddress((void**)&ul,   g_u_lo);
    cudaGetSymbolAddress((void**)&oh,   g_o_hi);
    cudaGetSymbolAddress((void**)&ol,   g_o_lo);
    cudaGetSymbolAddress((void**)&h1h,  g_h1_hi);
    cudaGetSymbolAddress((void**)&h1l,  g_h1_lo);
    cudaGetSymbolAddress((void**)&wth,  g_wt_hi);
    cudaGetSymbolAddress((void**)&wtl,  g_wt_lo);

    const int SMEM128 = 2 * (2 * 128 * ASTRIDE * 2 + 2 * 128 * ASTRIDE * 2);
    const int SMEM64  = 2 * (2 * 64  * ASTRIDE * 2 + 2 * 128 * ASTRIDE * 2);
    cudaFuncSetAttribute(gemm_tc<0,128>, cudaFuncAttributeMaxDynamicSharedMemorySize, SMEM128);
    cudaFuncSetAttribute(gemm_tc<1,128>, cudaFuncAttributeMaxDynamicSharedMemorySize, SMEM128);
    cudaFuncSetAttribute(gemm_tc<0,64>,  cudaFuncAttributeMaxDynamicSharedMemorySize, SMEM64);
    cudaFuncSetAttribute(attn_kernel,    cudaFuncAttributeMaxDynamicSharedMemorySize, ATTN_SMEM);

    // launch order fixed so ncu (-s 5 -c 1) profiles attn_kernel (layer 0):
    // 0: wsplit_all  1: biaspack  2: stats  3: embed  4: QKV gemm  5: attn
    wsplit_all_kernel<<<dim3(256, 6, NLAYERS), 256>>>(WQ, WK, WV, WO, F1, F2);
    biaspack_kernel<<<(NLAYERS * 768 + 255) / 256, 256>>>(bQ, bK, bV);
    stats_kernel<<<BROWS, 256>>>(z);
    embed_kernel<<<dim3(TOTAL_S, BROWS), 256>>>(z, revin_w, revin_b,
                                                Wf, bf, Wc, bcoarse, Wpos);

    for (int l = 0; l < NLAYERS; l++) {
        const size_t L = (size_t)l * WSTRIDE;
        gemm_tc<0,128><<<dim3(6, 40), 256, SMEM128>>>(
            uh, ul, wth + L + WOFF_Q, wtl + L + WOFF_Q,
            bqkv + l * 768, qkv, nullptr, nullptr, 768, D_MODEL);
        attn_kernel<<<BROWS * NHEADS, 256, ATTN_SMEM>>>(l > 0 ? 1 : 0,
                                                        l < NLAYERS - 1 ? 1 : 0);
        gemm_tc<0,64><<<dim3(2, 80), 256, SMEM64>>>(
            oh, ol, wth + L + WOFF_O, wtl + L + WOFF_O,
            bO + l * D_MODEL, tmp, nullptr, nullptr, D_MODEL, D_MODEL);
        resid_ln_kernel<<<SEQ, 256>>>(tmp, ln1_s + l * D_MODEL, ln1_b + l * D_MODEL);
        gemm_tc<1,128><<<dim3(8, 40), 256, SMEM128>>>(
            uh, ul, wth + L + WOFF_F1, wtl + L + WOFF_F1,
            c1 + l * DFF, nullptr, h1h, h1l, DFF, D_MODEL);
        gemm_tc<0,64><<<dim3(2, 80), 256, SMEM64>>>(
            h1h, h1l, wth + L + WOFF_F2, wtl + L + WOFF_F2,
            c2 + l * D_MODEL, tmp, nullptr, nullptr, D_MODEL, DFF);
        resid_ln_kernel<<<SEQ, 256>>>(tmp, ln2_s + l * D_MODEL, ln2_b + l * D_MODEL);
    }

    head_partial_kernel<<<D_MODEL, 96>>>(Wh);
    head_reduce_kernel<<<6, 256>>>(bh, revin_w, revin_b, out);
}

// round 6
// speedup vs baseline: 1.6023x; 1.0550x over previous
#include <cuda_runtime.h>
#include <cuda_bf16.h>
#include <math.h>
#include <stdint.h>

#define CTX      1024
#define BROWS    16
#define TOTAL_S  320
#define NF       256
#define D_MODEL  256
#define NHEADS   16
#define DK       16
#define DFF      1024
#define NLAYERS  4
#define TGT      96
#define SEQ      (BROWS * TOTAL_S)   // 5120
#define ATTN_SCALE 0.25f
#define LN_EPS   1e-5f

// ---------------------------------------------------------------------------
// warp MMA + cp.async helpers (sm_80+ path; tcgen05 unavailable at sm_103)
// ---------------------------------------------------------------------------
__device__ __forceinline__ uint32_t smem_u32(const void* p) {
    uint32_t a;
    asm("{ .reg .u64 t; cvta.to.shared.u64 t, %1; cvt.u32.u64 %0, t; }"
        : "=r"(a) : "l"(p));
    return a;
}
__device__ __forceinline__ void ldsm_x4(uint32_t& r0, uint32_t& r1,
                                        uint32_t& r2, uint32_t& r3, uint32_t addr) {
    asm volatile("ldmatrix.sync.aligned.m8n8.x4.shared.b16 {%0,%1,%2,%3}, [%4];"
                 : "=r"(r0), "=r"(r1), "=r"(r2), "=r"(r3) : "r"(addr));
}
__device__ __forceinline__ void mma_bf16(float* c, const uint32_t* a, const uint32_t* b) {
    asm volatile(
        "mma.sync.aligned.m16n8k16.row.col.f32.bf16.bf16.f32 "
        "{%0,%1,%2,%3}, {%4,%5,%6,%7}, {%8,%9}, {%0,%1,%2,%3};"
        : "+f"(c[0]), "+f"(c[1]), "+f"(c[2]), "+f"(c[3])
        : "r"(a[0]), "r"(a[1]), "r"(a[2]), "r"(a[3]), "r"(b[0]), "r"(b[1]));
}
#define CP_ASYNC16(dst, src) \
    asm volatile("cp.async.cg.shared.global [%0], [%1], 16;" :: "r"(dst), "l"(src))
#define CP_COMMIT() asm volatile("cp.async.commit_group;" ::: "memory")
#define CP_WAIT0()  asm volatile("cp.async.wait_group 0;" ::: "memory")

// ---------------------------------------------------------------------------
// scratch
// ---------------------------------------------------------------------------
__device__ __align__(256) float g_u[SEQ * D_MODEL];
__device__ __align__(256) float g_qkv[SEQ * 768];
__device__ __align__(256) float g_tmp[SEQ * D_MODEL];
__device__ __align__(256) float g_scores[BROWS * NHEADS * TOTAL_S * TOTAL_S];
__device__ float g_mean[BROWS];
__device__ float g_std[BROWS];
__device__ __align__(256) float g_part[D_MODEL * BROWS * TGT];
__device__ __align__(256) float g_bqkv[NLAYERS * 768];

__device__ __align__(256) __nv_bfloat16 g_u_hi[SEQ * D_MODEL];
__device__ __align__(256) __nv_bfloat16 g_u_lo[SEQ * D_MODEL];
__device__ __align__(256) __nv_bfloat16 g_o_hi[SEQ * D_MODEL];
__device__ __align__(256) __nv_bfloat16 g_o_lo[SEQ * D_MODEL];
__device__ __align__(256) __nv_bfloat16 g_h1_hi[SEQ * DFF];
__device__ __align__(256) __nv_bfloat16 g_h1_lo[SEQ * DFF];
#define WOFF_Q   0
#define WOFF_K   65536
#define WOFF_V   131072
#define WOFF_O   196608
#define WOFF_F1  262144
#define WOFF_F2  524288
#define WSTRIDE  786432
__device__ __align__(256) __nv_bfloat16 g_wt_hi[NLAYERS * WSTRIDE];
__device__ __align__(256) __nv_bfloat16 g_wt_lo[NLAYERS * WSTRIDE];

// ---------------------------------------------------------------------------
// merged weight transpose + split (all 6 matrices x 4 layers, one launch)
// ---------------------------------------------------------------------------
__global__ __launch_bounds__(256) void wsplit_all_kernel(
    const float* __restrict__ WQ, const float* __restrict__ WK,
    const float* __restrict__ WV, const float* __restrict__ WO,
    const float* __restrict__ F1, const float* __restrict__ F2)
{
    int kind = blockIdx.y, l = blockIdx.z, tile = blockIdx.x;
    const float* W; int R, C; size_t inl, ooff;
    switch (kind) {
        case 0: W = WQ; R = 256;  C = 256;  inl = 65536;  ooff = WOFF_Q;  break;
        case 1: W = WK; R = 256;  C = 256;  inl = 65536;  ooff = WOFF_K;  break;
        case 2: W = WV; R = 256;  C = 256;  inl = 65536;  ooff = WOFF_V;  break;
        case 3: W = WO; R = 256;  C = 256;  inl = 65536;  ooff = WOFF_O;  break;
        case 4: W = F1; R = 256;  C = 1024; inl = 262144; ooff = WOFF_F1; break;
        default: W = F2; R = 1024; C = 256; inl = 262144; ooff = WOFF_F2; break;
    }
    int ct = C >> 5, rt = R >> 5;
    if (tile >= ct * rt) return;
    int c0 = (tile % ct) << 5, r0 = (tile / ct) << 5;
    const float* Wl = W + (size_t)l * inl;

    __shared__ float t[32][33];
    int tx = threadIdx.x & 31, ty = threadIdx.x >> 5;
#pragma unroll
    for (int i = 0; i < 32; i += 8)
        t[ty + i][tx] = Wl[(size_t)(r0 + ty + i) * C + c0 + tx];
    __syncthreads();
#pragma unroll
    for (int i = 0; i < 32; i += 8) {
        float x = t[tx][ty + i];
        size_t oi = (size_t)l * WSTRIDE + ooff + (size_t)(c0 + ty + i) * R + (r0 + tx);
        __nv_bfloat16 h = __float2bfloat16(x);
        g_wt_hi[oi] = h;
        g_wt_lo[oi] = __float2bfloat16(x - __bfloat162float(h));
    }
}

__global__ __launch_bounds__(256) void biaspack_kernel(
    const float* __restrict__ bQ, const float* __restrict__ bK,
    const float* __restrict__ bV)
{
    int i = blockIdx.x * 256 + threadIdx.x;
    if (i >= NLAYERS * 768) return;
    int l = i / 768, j = i % 768;
    float v = (j < 256) ? bQ[l * 256 + j]
            : (j < 512) ? bK[l * 256 + j - 256]
                        : bV[l * 256 + j - 512];
    g_bqkv[i] = v;
}

// ---------------------------------------------------------------------------
__global__ __launch_bounds__(256) void stats_kernel(const float* __restrict__ z) {
    int r = blockIdx.x;
    int tid = threadIdx.x;
    float s = 0.f, s2 = 0.f;
    for (int i = tid; i < CTX; i += 256) {
        float v = z[r * CTX + i];
        s += v; s2 += v * v;
    }
    __shared__ float rs[256], rq[256];
    rs[tid] = s; rq[tid] = s2;
    __syncthreads();
    for (int o = 128; o; o >>= 1) {
        if (tid < o) { rs[tid] += rs[tid + o]; rq[tid] += rq[tid + o]; }
        __syncthreads();
    }
    if (tid == 0) {
        float m = rs[0] / CTX;
        float var = rq[0] / CTX - m * m;
        g_mean[r] = m;
        g_std[r]  = sqrtf(var + LN_EPS);
    }
}

// ---------------------------------------------------------------------------
__global__ __launch_bounds__(256) void embed_kernel(
    const float* __restrict__ z,
    const float* __restrict__ revin_w, const float* __restrict__ revin_b,
    const float* __restrict__ Wf, const float* __restrict__ bf,
    const float* __restrict__ Wc, const float* __restrict__ bcoarse,
    const float* __restrict__ Wpos)
{
    int bch = blockIdx.y;
    int s   = blockIdx.x;
    int d   = threadIdx.x;
    int c   = bch & 7;

    __shared__ float patch[32];
    int plen, stride, p;
    const float* W; const float* bias;
    if (s < NF) { plen = 8;  stride = 4;  p = s;      W = Wf; bias = bf; }
    else        { plen = 32; stride = 16; p = s - NF; W = Wc; bias = bcoarse; }

    if (d < plen) {
        int t = p * stride + d;
        if (t > CTX - 1) t = CTX - 1;
        float zv = z[bch * CTX + t];
        patch[d] = (zv - g_mean[bch]) / g_std[bch] * revin_w[c] + revin_b[c];
    }
    __syncthreads();

    float acc = bias[d] + Wpos[s * D_MODEL + d];
    for (int i = 0; i < plen; i++) acc += patch[i] * W[i * D_MODEL + d];
    size_t idx = (size_t)(bch * TOTAL_S + s) * D_MODEL + d;
    g_u[idx] = acc;
    __nv_bfloat16 h = __float2bfloat16(acc);
    g_u_hi[idx] = h;
    g_u_lo[idx] = __float2bfloat16(acc - __bfloat162float(h));
}

// ---------------------------------------------------------------------------
// HMMA bf16x3 GEMM, cp.async 2-stage pipeline. MT = CTA M-tile (64|128).
// ---------------------------------------------------------------------------
#define ASTRIDE 72

template<int EPI, int MT>
__global__ __launch_bounds__(256) void gemm_tc(
    const __nv_bfloat16* __restrict__ Ah, const __nv_bfloat16* __restrict__ Al,
    const __nv_bfloat16* __restrict__ Bh, const __nv_bfloat16* __restrict__ Bl,
    const float* __restrict__ bias,
    float* __restrict__ Cf,
    __nv_bfloat16* __restrict__ Chi, __nv_bfloat16* __restrict__ Clo,
    int N, int K)
{
    constexpr int WNs = (MT == 128) ? 2 : 4;
    constexpr int NT  = 16 / WNs;
    constexpr int BUF_A = MT * ASTRIDE * 2;
    constexpr int BUF_B = 128 * ASTRIDE * 2;
    constexpr int STAGE = 2 * BUF_A + 2 * BUF_B;

    extern __shared__ char smem[];
    const uint32_t sbase = smem_u32(smem);

    const int tid = threadIdx.x;
    const int bm = blockIdx.y * MT, bn = blockIdx.x * 128;
    const int warp = tid >> 5, lane = tid & 31;
    const int wm = warp / WNs, wn = warp % WNs;

    const int sr = tid >> 3, sc = (tid & 7) * 8;

    float acc[2][NT][4];
#pragma unroll
    for (int mt = 0; mt < 2; mt++)
#pragma unroll
        for (int nt = 0; nt < NT; nt++)
#pragma unroll
            for (int i = 0; i < 4; i++) acc[mt][nt][i] = 0.f;

    const int gg = lane >> 3, l7 = lane & 7;
    const int a_row = (gg & 1) * 8 + l7;
    const int a_kb  = (gg >> 1) * 16;
    const int b_row = (gg >> 1) * 8 + l7;
    const int b_kb  = (gg & 1) * 16;

    const int nchunk = K >> 6;

#define STAGE_LOAD(kc, s) do { \
        const int _k0 = (kc) << 6; \
        uint32_t _base = sbase + (s) * STAGE; \
        _Pragma("unroll") \
        for (int i = 0; i < MT / 32; i++) { \
            int r = sr + i * 32; \
            uint32_t so = _base + r * 144 + sc * 2; \
            CP_ASYNC16(so, Ah + (size_t)(bm + r) * K + _k0 + sc); \
            CP_ASYNC16(so + BUF_A, Al + (size_t)(bm + r) * K + _k0 + sc); \
        } \
        _Pragma("unroll") \
        for (int i = 0; i < 4; i++) { \
            int r = sr + i * 32; \
            uint32_t so = _base + 2 * BUF_A + r * 144 + sc * 2; \
            CP_ASYNC16(so, Bh + (size_t)(bn + r) * K + _k0 + sc); \
            CP_ASYNC16(so + BUF_B, Bl + (size_t)(bn + r) * K + _k0 + sc); \
        } \
        CP_COMMIT(); \
    } while (0)

    STAGE_LOAD(0, 0);

    for (int kc = 0; kc < nchunk; kc++) {
        CP_WAIT0();
        __syncthreads();
        if (kc + 1 < nchunk) STAGE_LOAD(kc + 1, (kc + 1) & 1);

        const uint32_t base = sbase + (kc & 1) * STAGE;
        const uint32_t uAh = base, uAl = base + BUF_A;
        const uint32_t uBh = base + 2 * BUF_A, uBl = uBh + BUF_B;

#pragma unroll
        for (int ks = 0; ks < 4; ks++) {
            uint32_t ah[2][4], al[2][4], bh[NT][2], bl[NT][2];
#pragma unroll
            for (int mt = 0; mt < 2; mt++) {
                int row = wm * 32 + mt * 16 + a_row;
                uint32_t off = (uint32_t)(row * 144 + ks * 32 + a_kb);
                ldsm_x4(ah[mt][0], ah[mt][1], ah[mt][2], ah[mt][3], uAh + off);
                ldsm_x4(al[mt][0], al[mt][1], al[mt][2], al[mt][3], uAl + off);
            }
#pragma unroll
            for (int j = 0; j < NT / 2; j++) {
                int row = wn * (128 / WNs) + j * 16 + b_row;
                uint32_t off = (uint32_t)(row * 144 + ks * 32 + b_kb);
                uint32_t r0, r1, r2, r3;
                ldsm_x4(r0, r1, r2, r3, uBh + off);
                bh[2 * j][0] = r0; bh[2 * j][1] = r1;
                bh[2 * j + 1][0] = r2; bh[2 * j + 1][1] = r3;
                ldsm_x4(r0, r1, r2, r3, uBl + off);
                bl[2 * j][0] = r0; bl[2 * j][1] = r1;
                bl[2 * j + 1][0] = r2; bl[2 * j + 1][1] = r3;
            }
#pragma unroll
            for (int mt = 0; mt < 2; mt++)
#pragma unroll
                for (int nt = 0; nt < NT; nt++) {
                    mma_bf16(acc[mt][nt], ah[mt], bh[nt]);
                    mma_bf16(acc[mt][nt], ah[mt], bl[nt]);
                    mma_bf16(acc[mt][nt], al[mt], bh[nt]);
                }
        }
        __syncthreads();
    }
#undef STAGE_LOAD

#pragma unroll
    for (int mt = 0; mt < 2; mt++) {
        int row0 = bm + wm * 32 + mt * 16 + (lane >> 2);
#pragma unroll
        for (int nt = 0; nt < NT; nt++) {
            int col = bn + wn * (128 / WNs) + nt * 8 + (lane & 3) * 2;
            float b0 = bias[col], b1 = bias[col + 1];
            float v0 = acc[mt][nt][0] + b0, v1 = acc[mt][nt][1] + b1;
            float v2 = acc[mt][nt][2] + b0, v3 = acc[mt][nt][3] + b1;
            if (EPI == 0) {
                float2 p0 = {v0, v1}, p1 = {v2, v3};
                *(float2*)&Cf[(size_t)row0 * N + col] = p0;
                *(float2*)&Cf[(size_t)(row0 + 8) * N + col] = p1;
            } else {
                v0 = 0.5f * v0 * (1.0f + erff(v0 * 0.7071067811865475f));
                v1 = 0.5f * v1 * (1.0f + erff(v1 * 0.7071067811865475f));
                v2 = 0.5f * v2 * (1.0f + erff(v2 * 0.7071067811865475f));
                v3 = 0.5f * v3 * (1.0f + erff(v3 * 0.7071067811865475f));
                __nv_bfloat162 hh, ll;
                hh.x = __float2bfloat16(v0); hh.y = __float2bfloat16(v1);
                ll.x = __float2bfloat16(v0 - __bfloat162float(hh.x));
                ll.y = __float2bfloat16(v1 - __bfloat162float(hh.y));
                *(__nv_bfloat162*)&Chi[(size_t)row0 * N + col] = hh;
                *(__nv_bfloat162*)&Clo[(size_t)row0 * N + col] = ll;
                hh.x = __float2bfloat16(v2); hh.y = __float2bfloat16(v3);
                ll.x = __float2bfloat16(v2 - __bfloat162float(hh.x));
                ll.y = __float2bfloat16(v3 - __bfloat162float(hh.y));
                *(__nv_bfloat162*)&Chi[(size_t)(row0 + 8) * N + col] = hh;
                *(__nv_bfloat162*)&Clo[(size_t)(row0 + 8) * N + col] = ll;
            }
        }
    }
}

// ---------------------------------------------------------------------------
// fused attention: grid (5 q-tiles, 256 bh), 256 threads, 8 rows per warp.
// K/V/Q(64-row slice) staged in smem; o written as bf16 hi/lo;
// score write skipped on last layer.
// ---------------------------------------------------------------------------
__global__ __launch_bounds__(256) void attn_kernel(int use_prev, int wr)
{
    __shared__ float Ks[TOTAL_S][17];
    __shared__ float Vs[TOTAL_S][17];
    __shared__ float Qs[64][17];

    int bh = blockIdx.y;
    int bc = bh >> 4, h = bh & 15;
    int q0 = blockIdx.x * 64;

    int tid = threadIdx.x;
    for (int i = tid; i < TOTAL_S * DK; i += 256) {
        int s = i >> 4, d = i & 15;
        size_t gi = (size_t)(bc * TOTAL_S + s) * 768 + (h << 4) + d;
        Ks[s][d] = g_qkv[gi + 256];
        Vs[s][d] = g_qkv[gi + 512];
    }
    for (int i = tid; i < 64 * DK; i += 256) {
        int s = i >> 4, d = i & 15;
        Qs[s][d] = g_qkv[(size_t)(bc * TOTAL_S + q0 + s) * 768 + (h << 4) + d];
    }
    __syncthreads();

    int warp = tid >> 5, lane = tid & 31;
    for (int it = 0; it < 8; it++) {
        int qr = warp * 8 + it;          // 0..63 within tile
        int qi = q0 + qr;
        float qv[DK];
#pragma unroll
        for (int d = 0; d < DK; d++) qv[d] = Qs[qr][d];

        float* srow = &g_scores[((size_t)bh * TOTAL_S + qi) * TOTAL_S];
        float sc[10];
#pragma unroll
        for (int j = 0; j < 10; j++) {
            int kk = j * 32 + lane;
            float acc = 0.f;
#pragma unroll
            for (int d = 0; d < DK; d++) acc += qv[d] * Ks[kk][d];
            acc *= ATTN_SCALE;
            if (use_prev) acc += srow[kk];
            sc[j] = acc;
            if (wr) srow[kk] = acc;
        }
        float m = sc[0];
#pragma unroll
        for (int j = 1; j < 10; j++) m = fmaxf(m, sc[j]);
#pragma unroll
        for (int o = 16; o; o >>= 1) m = fmaxf(m, __shfl_xor_sync(0xffffffffu, m, o));
        float sum = 0.f;
#pragma unroll
        for (int j = 0; j < 10; j++) { sc[j] = __expf(sc[j] - m); sum += sc[j]; }
#pragma unroll
        for (int o = 16; o; o >>= 1) sum += __shfl_xor_sync(0xffffffffu, sum, o);
        float inv = 1.f / sum;

        float oacc[DK];
#pragma unroll
        for (int d = 0; d < DK; d++) oacc[d] = 0.f;
#pragma unroll
        for (int j = 0; j < 10; j++) {
            int kk = j * 32 + lane;
            float wgt = sc[j] * inv;
#pragma unroll
            for (int d = 0; d < DK; d++) oacc[d] += wgt * Vs[kk][d];
        }
#pragma unroll
        for (int d = 0; d < DK; d++) {
#pragma unroll
            for (int o = 16; o; o >>= 1)
                oacc[d] += __shfl_xor_sync(0xffffffffu, oacc[d], o);
        }
        if (lane < DK) {
            float val = oacc[lane];
            size_t oi = (size_t)(bc * TOTAL_S + qi) * D_MODEL + (h << 4) + lane;
            __nv_bfloat16 hh = __float2bfloat16(val);
            g_o_hi[oi] = hh;
            g_o_lo[oi] = __float2bfloat16(val - __bfloat162float(hh));
        }
    }
}

// ---------------------------------------------------------------------------
__global__ __launch_bounds__(256) void resid_ln_kernel(
    const float* __restrict__ delta,
    const float* __restrict__ gs, const float* __restrict__ gb)
{
    int row = blockIdx.x;
    int d = threadIdx.x;
    int warp = d >> 5, lane = d & 31;
    size_t idx = (size_t)row * D_MODEL + d;
    float t = g_u[idx] + delta[idx];

    __shared__ float sred[8];
    float ws = t;
#pragma unroll
    for (int o = 16; o; o >>= 1) ws += __shfl_xor_sync(0xffffffffu, ws, o);
    if (lane == 0) sred[warp] = ws;
    __syncthreads();
    float tot = 0.f;
#pragma unroll
    for (int i = 0; i < 8; i++) tot += sred[i];
    float mean = tot * (1.0f / D_MODEL);
    __syncthreads();

    float df = t - mean;
    ws = df * df;
#pragma unroll
    for (int o = 16; o; o >>= 1) ws += __shfl_xor_sync(0xffffffffu, ws, o);
    if (lane == 0) sred[warp] = ws;
    __syncthreads();
    tot = 0.f;
#pragma unroll
    for (int i = 0; i < 8; i++) tot += sred[i];
    float var = tot * (1.0f / D_MODEL);

    float y = df * rsqrtf(var + LN_EPS) * gs[d] + gb[d];
    g_u[idx] = y;
    __nv_bfloat16 h = __float2bfloat16(y);
    g_u_hi[idx] = h;
    g_u_lo[idx] = __float2bfloat16(y - __bfloat162float(h));
}

// ---------------------------------------------------------------------------
__global__ __launch_bounds__(96) void head_partial_kernel(const float* __restrict__ Wh)
{
    int d = blockIdx.x;
    int t = threadIdx.x;
    __shared__ float usm[BROWS][TOTAL_S];
    for (int i = t; i < BROWS * TOTAL_S; i += 96) {
        int bcc = i / TOTAL_S, s = i % TOTAL_S;
        usm[bcc][s] = g_u[(size_t)(bcc * TOTAL_S + s) * D_MODEL + d];
    }
    __syncthreads();
    float acc[BROWS];
#pragma unroll
    for (int b = 0; b < BROWS; b++) acc[b] = 0.f;
    for (int s = 0; s < TOTAL_S; s++) {
        float w = Wh[((size_t)d * TOTAL_S + s) * TGT + t];
#pragma unroll
        for (int b = 0; b < BROWS; b++) acc[b] += usm[b][s] * w;
    }
#pragma unroll
    for (int b = 0; b < BROWS; b++)
        g_part[((size_t)d * BROWS + b) * TGT + t] = acc[b];
}

__global__ __launch_bounds__(256) void head_reduce_kernel(
    const float* __restrict__ bh,
    const float* __restrict__ revin_w, const float* __restrict__ revin_b,
    float* __restrict__ out)
{
    int idx = blockIdx.x * blockDim.x + threadIdx.x;
    if (idx >= BROWS * TGT) return;
    int bcc = idx / TGT, t = idx % TGT;
    float acc = 0.f;
    for (int d = 0; d < D_MODEL; d++)
        acc += g_part[((size_t)d * BROWS + bcc) * TGT + t];
    acc += bh[t];
    int c = bcc & 7;
    out[idx] = (acc - revin_b[c]) / (revin_w[c] + 1e-10f) * g_std[bcc] + g_mean[bcc];
}

// ---------------------------------------------------------------------------
extern "C" void kernel_launch(void* const* d_in, const int* in_sizes, int n_in,
                              void* d_out, int out_size)
{
    const float* z       = (const float*)d_in[0];
    const float* revin_w = (const float*)d_in[1];
    const float* revin_b = (const float*)d_in[2];
    const float* Wf      = (const float*)d_in[3];
    const float* bf      = (const float*)d_in[4];
    const float* Wc      = (const float*)d_in[5];
    const float* bcoarse = (const float*)d_in[6];
    const float* Wpos    = (const float*)d_in[7];
    const float* WQ      = (const float*)d_in[8];
    const float* bQ      = (const float*)d_in[9];
    const float* WK      = (const float*)d_in[10];
    const float* bK      = (const float*)d_in[11];
    const float* WV      = (const float*)d_in[12];
    const float* bV      = (const float*)d_in[13];
    const float* WO      = (const float*)d_in[14];
    const float* bO      = (const float*)d_in[15];
    const float* ln1_s   = (const float*)d_in[16];
    const float* ln1_b   = (const float*)d_in[17];
    const float* ln2_s   = (const float*)d_in[18];
    const float* ln2_b   = (const float*)d_in[19];
    const float* F1      = (const float*)d_in[20];
    const float* c1      = (const float*)d_in[21];
    const float* F2      = (const float*)d_in[22];
    const float* c2      = (const float*)d_in[23];
    const float* Wh      = (const float*)d_in[24];
    const float* bh      = (const float*)d_in[25];
    float* out = (float*)d_out;

    float *u, *qkv, *tmp, *bqkv;
    __nv_bfloat16 *uh, *ul, *oh, *ol, *h1h, *h1l, *wth, *wtl;
    cudaGetSymbolAddress((void**)&u,    g_u);
    cudaGetSymbolAddress((void**)&qkv,  g_qkv);
    cudaGetSymbolAddress((void**)&tmp,  g_tmp);
    cudaGetSymbolAddress((void**)&bqkv, g_bqkv);
    cudaGetSymbolAddress((void**)&uh,   g_u_hi);
    cudaGetSymbolAddress((void**)&ul,   g_u_lo);
    cudaGetSymbolAddress((void**)&oh,   g_o_hi);
    cudaGetSymbolAddress((void**)&ol,   g_o_lo);
    cudaGetSymbolAddress((void**)&h1h,  g_h1_hi);
    cudaGetSymbolAddress((void**)&h1l,  g_h1_lo);
    cudaGetSymbolAddress((void**)&wth,  g_wt_hi);
    cudaGetSymbolAddress((void**)&wtl,  g_wt_lo);

    const int SMEM128 = 2 * (2 * 128 * ASTRIDE * 2 + 2 * 128 * ASTRIDE * 2);
    const int SMEM64  = 2 * (2 * 64  * ASTRIDE * 2 + 2 * 128 * ASTRIDE * 2);
    cudaFuncSetAttribute(gemm_tc<0,128>, cudaFuncAttributeMaxDynamicSharedMemorySize, SMEM128);
    cudaFuncSetAttribute(gemm_tc<1,128>, cudaFuncAttributeMaxDynamicSharedMemorySize, SMEM128);
    cudaFuncSetAttribute(gemm_tc<0,64>,  cudaFuncAttributeMaxDynamicSharedMemorySize, SMEM64);

    wsplit_all_kernel<<<dim3(256, 6, NLAYERS), 256>>>(WQ, WK, WV, WO, F1, F2);
    biaspack_kernel<<<(NLAYERS * 768 + 255) / 256, 256>>>(bQ, bK, bV);
    stats_kernel<<<BROWS, 256>>>(z);
    embed_kernel<<<dim3(TOTAL_S, BROWS), 256>>>(z, revin_w, revin_b,
                                                Wf, bf, Wc, bcoarse, Wpos);

    for (int l = 0; l < NLAYERS; l++) {
        const size_t L = (size_t)l * WSTRIDE;
        gemm_tc<0,128><<<dim3(6, 40), 256, SMEM128>>>(
            uh, ul, wth + L + WOFF_Q, wtl + L + WOFF_Q,
            bqkv + l * 768, qkv, nullptr, nullptr, 768, D_MODEL);
        attn_kernel<<<dim3(5, BROWS * NHEADS), 256>>>(l > 0 ? 1 : 0,
                                                      l < NLAYERS - 1 ? 1 : 0);
        gemm_tc<0,64><<<dim3(2, 80), 256, SMEM64>>>(
            oh, ol, wth + L + WOFF_O, wtl + L + WOFF_O,
            bO + l * D_MODEL, tmp, nullptr, nullptr, D_MODEL, D_MODEL);
        resid_ln_kernel<<<SEQ, 256>>>(tmp, ln1_s + l * D_MODEL, ln1_b + l * D_MODEL);
        gemm_tc<1,128><<<dim3(8, 40), 256, SMEM128>>>(
            uh, ul, wth + L + WOFF_F1, wtl + L + WOFF_F1,
            c1 + l * DFF, nullptr, h1h, h1l, DFF, D_MODEL);
        gemm_tc<0,64><<<dim3(2, 80), 256, SMEM64>>>(
            h1h, h1l, wth + L + WOFF_F2, wtl + L + WOFF_F2,
            c2 + l * D_MODEL, tmp, nullptr, nullptr, D_MODEL, DFF);
        resid_ln_kernel<<<SEQ, 256>>>(tmp, ln2_s + l * D_MODEL, ln2_b + l * D_MODEL);
    }

    head_partial_kernel<<<D_MODEL, 96>>>(Wh);
    head_reduce_kernel<<<6, 256>>>(bh, revin_w, revin_b, out);
}